// round 9
// baseline (speedup 1.0000x reference)
#include <cuda_runtime.h>
#include <cuda_bf16.h>
#include <cstdint>

// Problem constants
#define Bn   16
#define Nn   4096
#define Mn   1024
#define C1n  128
#define C2n  256
#define CINn 384
#define H1n  256
#define H2n  128

// ---------------- helpers ----------------
__device__ __forceinline__ uint32_t smem_u32(const void* p) {
    uint32_t a;
    asm("{ .reg .u64 t; cvta.to.shared.u64 t, %1; cvt.u32.u64 %0, t; }" : "=r"(a) : "l"(p));
    return a;
}
__device__ __forceinline__ void ldsm4(uint32_t* r, uint32_t addr) {
    asm volatile("ldmatrix.sync.aligned.m8n8.x4.shared.b16 {%0,%1,%2,%3}, [%4];"
        : "=r"(r[0]), "=r"(r[1]), "=r"(r[2]), "=r"(r[3]) : "r"(addr));
}
__device__ __forceinline__ void ldsm4t(uint32_t* r, uint32_t addr) {
    asm volatile("ldmatrix.sync.aligned.m8n8.x4.trans.shared.b16 {%0,%1,%2,%3}, [%4];"
        : "=r"(r[0]), "=r"(r[1]), "=r"(r[2]), "=r"(r[3]) : "r"(addr));
}
__device__ __forceinline__ void mma_bf16(float* d, const uint32_t* a, const uint32_t* b) {
    asm volatile("mma.sync.aligned.m16n8k16.row.col.f32.bf16.bf16.f32 "
        "{%0,%1,%2,%3}, {%4,%5,%6,%7}, {%8,%9}, {%0,%1,%2,%3};"
        : "+f"(d[0]), "+f"(d[1]), "+f"(d[2]), "+f"(d[3])
        : "r"(a[0]), "r"(a[1]), "r"(a[2]), "r"(a[3]), "r"(b[0]), "r"(b[1]));
}
__device__ __forceinline__ uint32_t bfhi2(float a, float b) {
    return __byte_perm(__float_as_uint(a), __float_as_uint(b), 0x7632);
}
__device__ __forceinline__ uint32_t bflo2(float a, float b) {
    const float la = a - __uint_as_float(__float_as_uint(a) & 0xFFFF0000u);
    const float lb = b - __uint_as_float(__float_as_uint(b) & 0xFFFF0000u);
    __nv_bfloat162 p = __floats2bfloat162_rn(la, lb);
    return *(uint32_t*)&p;
}
#define CP16(dst, src) asm volatile("cp.async.cg.shared.global [%0], [%1], 16;" :: "r"(dst), "l"(src))
#define CPCOMMIT()     asm volatile("cp.async.commit_group;" ::: "memory")
#define CPWAIT(n)      asm volatile("cp.async.wait_group %0;" :: "n"(n) : "memory")

// device scratch
__device__ float    g_interp[(size_t)Bn * C2n * Nn];
__device__ uint16_t g_p2h[(size_t)Bn * C2n * Mn];
__device__ uint16_t g_p2l[(size_t)Bn * C2n * Mn];

// prep: split p2 fp32 -> bf16 hi/lo
__global__ void split_p2(const float* __restrict__ src)
{
    const size_t i = (size_t)blockIdx.x * 256 + threadIdx.x;   // float4 index
    const float4 v = ((const float4*)src)[i];
    uint2 h, l;
    h.x = bfhi2(v.x, v.y); h.y = bfhi2(v.z, v.w);
    l.x = bflo2(v.x, v.y); l.y = bflo2(v.z, v.w);
    ((uint2*)g_p2h)[i] = h;
    ((uint2*)g_p2l)[i] = l;
}

// paired-row address: two logical 64B rows per 144B physical row (conflict-free ldsm)
#define PR(r) (((r) >> 1) * 144 + ((r) & 1) * 64)

// ================= Kernel 1: interpolation via mma.sync =================
// CTA: 64 n x 256 c.  K = M = 1024 in 32-chunks, double-buffered, occ 2.
// A [64n][32k] pitch 80 (SIMT fill); B [256c][32k] paired rows (cp.async).
#define IA(buf, part)  ((buf) * 10240 + (part) * 5120)
#define IB(buf, part)  (20480 + (buf) * 36864 + (part) * 18432)
#define IOFF_X2  94208              // SoA: x[1024], y[1024], z[1024]
#define IOFF_DS  106496
#define IOFF_DEN 107520
#define ISMB     107776

__global__ __launch_bounds__(256, 2)
void interp_tc(const float* __restrict__ xyz1,
               const float* __restrict__ xyz2)
{
    extern __shared__ char smc[];
    const uint32_t sb = smem_u32(smc);
    float* s_x2x = (float*)(smc + IOFF_X2);
    float* s_x2y = s_x2x + Mn;
    float* s_x2z = s_x2x + 2 * Mn;
    float* s_ds  = (float*)(smc + IOFF_DS);
    float* s_den = (float*)(smc + IOFF_DEN);

    const int tid = threadIdx.x, w = tid >> 5, lane = tid & 31;
    const int b = blockIdx.y, n0 = blockIdx.x * 64;

    // xyz2 -> SoA smem
    for (int m = tid; m < Mn; m += 256) {
        const float3 v = ((const float3*)(xyz2 + (size_t)b * Mn * 3))[m];
        s_x2x[m] = v.x; s_x2y[m] = v.y; s_x2z[m] = v.z;
    }
    __syncthreads();

    const int nf = tid & 63;        // point this thread generates weights for
    const int g  = tid >> 6;        // 8-m group within 32-chunk
    const float px = xyz1[((size_t)b * Nn + n0 + nf) * 3 + 0];
    const float py = xyz1[((size_t)b * Nn + n0 + nf) * 3 + 1];
    const float pz = xyz1[((size_t)b * Nn + n0 + nf) * 3 + 2];
    float dsum = 0.f;

    const int mw = w & 1, cw = w >> 1;   // warp tile: 32 n x 64 c
    float acc[16][4];
    #pragma unroll
    for (int i = 0; i < 16; i++)
        #pragma unroll
        for (int j = 0; j < 4; j++) acc[i][j] = 0.f;

    const size_t p2base = (size_t)b * C2n * Mn;

    // A fill: SIMT rsqrt weights hi/lo; _dm gates dsum (0 for the dummy tail fill)
    #define FILLA(_bufv, _m0v, _dm) do {                                           \
        const int _mb = (_m0v) + g * 8;                                            \
        const float4 xa = *(const float4*)&s_x2x[_mb];                             \
        const float4 xbv = *(const float4*)&s_x2x[_mb + 4];                        \
        const float4 ya = *(const float4*)&s_x2y[_mb];                             \
        const float4 yb = *(const float4*)&s_x2y[_mb + 4];                         \
        const float4 za = *(const float4*)&s_x2z[_mb];                             \
        const float4 zb = *(const float4*)&s_x2z[_mb + 4];                         \
        const float xs[8] = {xa.x, xa.y, xa.z, xa.w, xbv.x, xbv.y, xbv.z, xbv.w};  \
        const float ys[8] = {ya.x, ya.y, ya.z, ya.w, yb.x, yb.y, yb.z, yb.w};      \
        const float zs[8] = {za.x, za.y, za.z, za.w, zb.x, zb.y, zb.z, zb.w};      \
        float iv[8];                                                               \
        _Pragma("unroll")                                                          \
        for (int t = 0; t < 8; t++) {                                              \
            const float dx = px - xs[t];                                           \
            const float dy = py - ys[t];                                           \
            const float dz = pz - zs[t];                                           \
            const float d2 = fmaf(dx, dx, fmaf(dy, dy, fmaf(dz, dz, 1e-16f)));     \
            iv[t] = rsqrtf(d2);                                                    \
            dsum = fmaf(iv[t], (_dm), dsum);                                       \
        }                                                                          \
        uint4 hv, lv;                                                              \
        hv.x = bfhi2(iv[0], iv[1]); hv.y = bfhi2(iv[2], iv[3]);                    \
        hv.z = bfhi2(iv[4], iv[5]); hv.w = bfhi2(iv[6], iv[7]);                    \
        lv.x = bflo2(iv[0], iv[1]); lv.y = bflo2(iv[2], iv[3]);                    \
        lv.z = bflo2(iv[4], iv[5]); lv.w = bflo2(iv[6], iv[7]);                    \
        *(uint4*)(smc + IA(_bufv, 0) + nf * 80 + g * 16) = hv;                     \
        *(uint4*)(smc + IA(_bufv, 1) + nf * 80 + g * 16) = lv;                     \
    } while (0)

    // B fill: cp.async pre-split p2 chunk, 8 x 16B per thread
    #define FILLB(_bufv, _m0v) do {                                                \
        _Pragma("unroll")                                                          \
        for (int it = 0; it < 8; it++) {                                           \
            const int u = tid + it * 256;                                          \
            const int part = u >> 10;                                              \
            const int v = u & 1023, c = v >> 2, s = v & 3;                         \
            const uint32_t dst = sb + IB(_bufv, part) + PR(c) + s * 16;            \
            const uint16_t* srcp = part ? g_p2l : g_p2h;                           \
            CP16(dst, srcp + p2base + (size_t)c * Mn + (_m0v) + s * 8);            \
        }                                                                          \
        CPCOMMIT();                                                                \
    } while (0)

    // one kk-slice of interp MMA (reads buffer `buf`)
    #define IMMA_KK(kkv) do {                                                      \
        uint32_t ah[2][4], al[2][4];                                               \
        _Pragma("unroll")                                                          \
        for (int mt = 0; mt < 2; mt++) {                                           \
            const uint32_t row = mw * 32 + mt * 16 + (lane & 15);                  \
            const uint32_t off = row * 80 + (kkv) * 32 + (lane >> 4) * 16;         \
            ldsm4(ah[mt], sb + IA(buf, 0) + off);                                  \
            ldsm4(al[mt], sb + IA(buf, 1) + off);                                  \
        }                                                                          \
        _Pragma("unroll")                                                          \
        for (int cp = 0; cp < 4; cp++) {                                           \
            const uint32_t c = cw * 64 + cp * 16 + (lane >> 4) * 8 + (lane & 7);   \
            const uint32_t off = PR(c) + (kkv) * 32 + ((lane >> 3) & 1) * 16;      \
            uint32_t rh[4], rl[4];                                                 \
            ldsm4(rh, sb + IB(buf, 0) + off);                                      \
            ldsm4(rl, sb + IB(buf, 1) + off);                                      \
            _Pragma("unroll")                                                      \
            for (int mt = 0; mt < 2; mt++) {                                       \
                mma_bf16(acc[mt * 8 + cp * 2],     ah[mt], rh);                    \
                mma_bf16(acc[mt * 8 + cp * 2 + 1], ah[mt], rh + 2);                \
                mma_bf16(acc[mt * 8 + cp * 2],     ah[mt], rl);                    \
                mma_bf16(acc[mt * 8 + cp * 2 + 1], ah[mt], rl + 2);                \
                mma_bf16(acc[mt * 8 + cp * 2],     al[mt], rh);                    \
                mma_bf16(acc[mt * 8 + cp * 2 + 1], al[mt], rh + 2);                \
            }                                                                      \
        }                                                                          \
    } while (0)

    FILLA(0, 0, 1.0f);
    FILLB(0, 0);

    for (int ch = 0; ch < 32; ch++) {
        const int buf = ch & 1;
        CPWAIT(0);
        __syncthreads();
        // next-chunk fill, unconditional (straight-line): index clamped; the
        // ch==31 tail writes the retired buffer (never read) with dsum gated off.
        const int chn  = ch + 1;
        const int bufn = chn & 1;
        const int m0n  = (chn > 31 ? 31 : chn) * 32;
        const float dmn = (chn > 31) ? 0.0f : 1.0f;

        FILLB(bufn, m0n);          // cp.async issued early, overlaps both MMA halves
        IMMA_KK(0);
        FILLA(bufn, m0n, dmn);     // FMA burst hides under kk=1 HMMA drain
        IMMA_KK(1);
    }
    #undef FILLA
    #undef FILLB
    #undef IMMA_KK

    CPWAIT(0);
    // denominator
    __syncthreads();
    s_ds[tid] = dsum;
    __syncthreads();
    if (tid < 64)
        s_den[tid] = 1.0f / (s_ds[tid] + s_ds[tid + 64] + s_ds[tid + 128] + s_ds[tid + 192]);
    __syncthreads();

    // epilogue: scale and store
    #pragma unroll
    for (int mt = 0; mt < 2; mt++) {
        const int nl = mw * 32 + mt * 16 + (lane >> 2);
        const float i0 = s_den[nl], i1 = s_den[nl + 8];
        #pragma unroll
        for (int ct = 0; ct < 8; ct++) {
            const int c = cw * 64 + ct * 8 + (lane & 3) * 2;
            float* d0 = &g_interp[((size_t)b * C2n + c) * Nn + n0];
            float* d1 = &g_interp[((size_t)b * C2n + c + 1) * Nn + n0];
            const float* a = acc[mt * 8 + ct];
            d0[nl]     = a[0] * i0;
            d1[nl]     = a[1] * i0;
            d0[nl + 8] = a[2] * i1;
            d1[nl + 8] = a[3] * i1;
        }
    }
}

// ================= Kernel 2: fused 2-layer MLP via mma.sync =================
// CTA: 64 n. GEMM1: 256o x 64n x K384 (32-chunks); GEMM2: 128o x 64n x K256.
#define MW(buf, part)   ((buf) * 36864 + (part) * 18432)          // W1 chunk [256o][32k] paired
#define MH(part)        ((part) * 36864)                           // h [256k][64n] (overlays MW)
#define MX(buf, part)   (73728 + (buf) * 9216 + (part) * 4608)     // x chunk [32k][64n]
#define MW2(buf, part)  (73728 + (buf) * 18432 + (part) * 9216)    // W2 chunk [128o][32k] paired
#define MOFF_B1  110592
#define MOFF_B2  111616
#define MSMB     112128

__global__ __launch_bounds__(256, 2)
void mlp_tc(const float* __restrict__ p1,
            const float* __restrict__ W1,
            const float* __restrict__ b1,
            const float* __restrict__ W2,
            const float* __restrict__ b2,
            float* __restrict__ out)
{
    extern __shared__ char smc[];
    const uint32_t sb = smem_u32(smc);
    float* s_b1 = (float*)(smc + MOFF_B1);
    float* s_b2 = (float*)(smc + MOFF_B2);

    const int tid = threadIdx.x, w = tid >> 5, lane = tid & 31;
    const int b = blockIdx.y, n0 = blockIdx.x * 64;

    s_b1[tid] = b1[tid];
    if (tid < H2n) s_b2[tid] = b2[tid];

    const int ow = w >> 1, nw = w & 1;   // GEMM1 warp: 64 o x 32 n

    #define FILLW1(_bufv, _kc) do {                                                 \
        _Pragma("unroll")                                                           \
        for (int it = 0; it < 8; it++) {                                            \
            const int u = tid + it * 256;                                           \
            const int o = u >> 3, q = u & 7;                                        \
            const float4 v = *(const float4*)&W1[(size_t)o * CINn + (_kc) * 32 + q * 4]; \
            uint2 hv, lv;                                                           \
            hv.x = bfhi2(v.x, v.y); hv.y = bfhi2(v.z, v.w);                         \
            lv.x = bflo2(v.x, v.y); lv.y = bflo2(v.z, v.w);                         \
            *(uint2*)(smc + MW(_bufv, 0) + PR(o) + q * 8) = hv;                     \
            *(uint2*)(smc + MW(_bufv, 1) + PR(o) + q * 8) = lv;                     \
        }                                                                           \
    } while (0)

    #define FILLX(_bufv, _kc) do {                                                  \
        _Pragma("unroll")                                                           \
        for (int it = 0; it < 2; it++) {                                            \
            const int u = tid + it * 256;                                           \
            const int k = u >> 4, q = u & 15;                                       \
            const int c = (_kc) * 32 + k;                                           \
            const float* src = (c < C1n)                                            \
                ? &p1[((size_t)b * C1n + c) * Nn]                                   \
                : &g_interp[((size_t)b * C2n + (c - C1n)) * Nn];                    \
            const float4 v = *(const float4*)&src[n0 + q * 4];                      \
            uint2 hv, lv;                                                           \
            hv.x = bfhi2(v.x, v.y); hv.y = bfhi2(v.z, v.w);                         \
            lv.x = bflo2(v.x, v.y); lv.y = bflo2(v.z, v.w);                         \
            *(uint2*)(smc + MX(_bufv, 0) + k * 144 + q * 8) = hv;                   \
            *(uint2*)(smc + MX(_bufv, 1) + k * 144 + q * 8) = lv;                   \
        }                                                                           \
    } while (0)

    // one kk-slice of GEMM1 MMA (reads buffer `buf`)
    #define MMA1_KK(kkv) do {                                                       \
        uint32_t wh[4][4], wl[4][4];                                                \
        _Pragma("unroll")                                                           \
        for (int mi = 0; mi < 4; mi++) {                                            \
            const uint32_t o = ow * 64 + mi * 16 + (lane & 15);                     \
            const uint32_t off = PR(o) + (kkv) * 32 + (lane >> 4) * 16;             \
            ldsm4(wh[mi], sb + MW(buf, 0) + off);                                   \
            ldsm4(wl[mi], sb + MW(buf, 1) + off);                                   \
        }                                                                           \
        uint32_t xh[4][2], xl[4][2];                                                \
        _Pragma("unroll")                                                           \
        for (int np = 0; np < 2; np++) {                                            \
            const uint32_t row  = (kkv) * 16 + ((lane >> 3) & 1) * 8 + (lane & 7);  \
            const uint32_t colb = (nw * 32 + np * 16) * 2 + (lane >> 4) * 16;       \
            uint32_t r[4];                                                          \
            ldsm4t(r, sb + MX(buf, 0) + row * 144 + colb);                          \
            xh[np * 2][0] = r[0]; xh[np * 2][1] = r[1];                             \
            xh[np * 2 + 1][0] = r[2]; xh[np * 2 + 1][1] = r[3];                     \
            ldsm4t(r, sb + MX(buf, 1) + row * 144 + colb);                          \
            xl[np * 2][0] = r[0]; xl[np * 2][1] = r[1];                             \
            xl[np * 2 + 1][0] = r[2]; xl[np * 2 + 1][1] = r[3];                     \
        }                                                                           \
        _Pragma("unroll")                                                           \
        for (int mi = 0; mi < 4; mi++)                                              \
            _Pragma("unroll")                                                       \
            for (int ni = 0; ni < 4; ni++) {                                        \
                mma_bf16(acc1[mi * 4 + ni], wh[mi], xh[ni]);                        \
                mma_bf16(acc1[mi * 4 + ni], wh[mi], xl[ni]);                        \
                mma_bf16(acc1[mi * 4 + ni], wl[mi], xh[ni]);                        \
            }                                                                       \
    } while (0)

    float acc1[16][4];
    #pragma unroll
    for (int i = 0; i < 16; i++)
        #pragma unroll
        for (int j = 0; j < 4; j++) acc1[i][j] = 0.f;

    FILLW1(0, 0); FILLX(0, 0);
    __syncthreads();

    for (int kc = 0; kc < 12; kc++) {
        const int buf = kc & 1;
        const int kn   = kc + 1;
        const int bufn = kn & 1;
        const int knc  = kn > 11 ? 11 : kn;   // tail writes retired buffer, never read

        MMA1_KK(0);
        FILLW1(bufn, knc);
        FILLX(bufn, knc);
        MMA1_KK(1);
        __syncthreads();
    }
    #undef FILLW1
    #undef FILLX
    #undef MMA1_KK

    #define FILLW2(_bufv, _kc) do {                                                 \
        _Pragma("unroll")                                                           \
        for (int it = 0; it < 4; it++) {                                            \
            const int u = tid + it * 256;                                           \
            const int o = u >> 3, q = u & 7;                                        \
            const float4 v = *(const float4*)&W2[(size_t)o * H1n + (_kc) * 32 + q * 4]; \
            uint2 hv, lv;                                                           \
            hv.x = bfhi2(v.x, v.y); hv.y = bfhi2(v.z, v.w);                         \
            lv.x = bflo2(v.x, v.y); lv.y = bflo2(v.z, v.w);                         \
            *(uint2*)(smc + MW2(_bufv, 0) + PR(o) + q * 8) = hv;                    \
            *(uint2*)(smc + MW2(_bufv, 1) + PR(o) + q * 8) = lv;                    \
        }                                                                           \
    } while (0)

    // one kk-slice of GEMM2 MMA (reads buffer `buf`)
    #define MMA2_KK(kkv) do {                                                       \
        uint32_t wh[2][4], wl[2][4];                                                \
        _Pragma("unroll")                                                           \
        for (int mi = 0; mi < 2; mi++) {                                            \
            const uint32_t o = ow2 * 32 + mi * 16 + (lane & 15);                    \
            const uint32_t off = PR(o) + (kkv) * 32 + (lane >> 4) * 16;             \
            ldsm4(wh[mi], sb + MW2(buf, 0) + off);                                  \
            ldsm4(wl[mi], sb + MW2(buf, 1) + off);                                  \
        }                                                                           \
        uint32_t hh[4][2], hl[4][2];                                                \
        _Pragma("unroll")                                                           \
        for (int np = 0; np < 2; np++) {                                            \
            const uint32_t row  = kc * 32 + (kkv) * 16 + ((lane >> 3) & 1) * 8 + (lane & 7); \
            const uint32_t colb = (nw * 32 + np * 16) * 2 + (lane >> 4) * 16;       \
            uint32_t r[4];                                                          \
            ldsm4t(r, sb + MH(0) + row * 144 + colb);                               \
            hh[np * 2][0] = r[0]; hh[np * 2][1] = r[1];                             \
            hh[np * 2 + 1][0] = r[2]; hh[np * 2 + 1][1] = r[3];                     \
            ldsm4t(r, sb + MH(1) + row * 144 + colb);                               \
            hl[np * 2][0] = r[0]; hl[np * 2][1] = r[1];                             \
            hl[np * 2 + 1][0] = r[2]; hl[np * 2 + 1][1] = r[3];                     \
        }                                                                           \
        _Pragma("unroll")                                                           \
        for (int mi = 0; mi < 2; mi++)                                              \
            _Pragma("unroll")                                                       \
            for (int ni = 0; ni < 4; ni++) {                                        \
                mma_bf16(acc2[mi * 4 + ni], wh[mi], hh[ni]);                        \
                mma_bf16(acc2[mi * 4 + ni], wh[mi], hl[ni]);                        \
                mma_bf16(acc2[mi * 4 + ni], wl[mi], hh[ni]);                        \
            }                                                                       \
    } while (0)

    // W1/x regions fully read; repurpose for W2 + h
    FILLW2(0, 0);

    // GEMM1 epilogue: relu + bias -> s_h [256 k-rows][64 n], hi/lo (overlays MW)
    #pragma unroll
    for (int mi = 0; mi < 4; mi++) {
        const int o = ow * 64 + mi * 16 + (lane >> 2);
        const float bia0 = s_b1[o], bia1 = s_b1[o + 8];
        #pragma unroll
        for (int ni = 0; ni < 4; ni++) {
            const int n = nw * 32 + ni * 8 + (lane & 3) * 2;
            const float* a = acc1[mi * 4 + ni];
            const float v0 = fmaxf(a[0] + bia0, 0.f);
            const float v1 = fmaxf(a[1] + bia0, 0.f);
            const float v2 = fmaxf(a[2] + bia1, 0.f);
            const float v3 = fmaxf(a[3] + bia1, 0.f);
            *(uint32_t*)(smc + MH(0) + o * 144 + n * 2)       = bfhi2(v0, v1);
            *(uint32_t*)(smc + MH(1) + o * 144 + n * 2)       = bflo2(v0, v1);
            *(uint32_t*)(smc + MH(0) + (o + 8) * 144 + n * 2) = bfhi2(v2, v3);
            *(uint32_t*)(smc + MH(1) + (o + 8) * 144 + n * 2) = bflo2(v2, v3);
        }
    }
    __syncthreads();

    // ---------- GEMM2 (distance-1 double buffer, fill between halves) ----------
    const int ow2 = w >> 1;   // 32 o per warp
    float acc2[8][4];
    #pragma unroll
    for (int i = 0; i < 8; i++)
        #pragma unroll
        for (int j = 0; j < 4; j++) acc2[i][j] = 0.f;

    for (int kc = 0; kc < 8; kc++) {
        const int buf = kc & 1;
        const int kn   = kc + 1;
        const int bufn = kn & 1;
        const int knc  = kn > 7 ? 7 : kn;     // tail writes retired buffer, never read

        MMA2_KK(0);
        FILLW2(bufn, knc);
        MMA2_KK(1);
        __syncthreads();
    }
    #undef FILLW2
    #undef MMA2_KK

    // ---------- output ----------
    #pragma unroll
    for (int mi = 0; mi < 2; mi++) {
        const int o = ow2 * 32 + mi * 16 + (lane >> 2);
        const float bia0 = s_b2[o], bia1 = s_b2[o + 8];
        #pragma unroll
        for (int ni = 0; ni < 4; ni++) {
            const int n = n0 + nw * 32 + ni * 8 + (lane & 3) * 2;
            const float* a = acc2[mi * 4 + ni];
            float2 v0, v1;
            v0.x = fmaxf(a[0] + bia0, 0.f);
            v0.y = fmaxf(a[1] + bia0, 0.f);
            v1.x = fmaxf(a[2] + bia1, 0.f);
            v1.y = fmaxf(a[3] + bia1, 0.f);
            *(float2*)&out[((size_t)b * H2n + o) * Nn + n]     = v0;
            *(float2*)&out[((size_t)b * H2n + o + 8) * Nn + n] = v1;
        }
    }
}

extern "C" void kernel_launch(void* const* d_in, const int* in_sizes, int n_in,
                              void* d_out, int out_size)
{
    const float* xyz1 = (const float*)d_in[0];
    const float* xyz2 = (const float*)d_in[1];
    const float* p1   = (const float*)d_in[2];
    const float* p2   = (const float*)d_in[3];
    const float* W1   = (const float*)d_in[4];
    const float* b1   = (const float*)d_in[5];
    const float* W2   = (const float*)d_in[6];
    const float* b2   = (const float*)d_in[7];
    float* out = (float*)d_out;

    cudaFuncSetAttribute(interp_tc, cudaFuncAttributeMaxDynamicSharedMemorySize, ISMB);
    cudaFuncSetAttribute(mlp_tc,    cudaFuncAttributeMaxDynamicSharedMemorySize, MSMB);

    split_p2<<<(Bn * C2n * Mn / 4) / 256, 256>>>(p2);
    dim3 grid(Nn / 64, Bn);
    interp_tc<<<grid, 256, ISMB>>>(xyz1, xyz2);
    mlp_tc<<<grid, 256, MSMB>>>(p1, W1, b1, W2, b2, out);
}

// round 10
// speedup vs baseline: 1.1022x; 1.1022x over previous
#include <cuda_runtime.h>
#include <cuda_bf16.h>
#include <cstdint>

// Problem constants
#define Bn   16
#define Nn   4096
#define Mn   1024
#define C1n  128
#define C2n  256
#define CINn 384
#define H1n  256
#define H2n  128

// ---------------- helpers ----------------
__device__ __forceinline__ uint32_t smem_u32(const void* p) {
    uint32_t a;
    asm("{ .reg .u64 t; cvta.to.shared.u64 t, %1; cvt.u32.u64 %0, t; }" : "=r"(a) : "l"(p));
    return a;
}
__device__ __forceinline__ void ldsm4(uint32_t* r, uint32_t addr) {
    asm volatile("ldmatrix.sync.aligned.m8n8.x4.shared.b16 {%0,%1,%2,%3}, [%4];"
        : "=r"(r[0]), "=r"(r[1]), "=r"(r[2]), "=r"(r[3]) : "r"(addr));
}
__device__ __forceinline__ void ldsm4t(uint32_t* r, uint32_t addr) {
    asm volatile("ldmatrix.sync.aligned.m8n8.x4.trans.shared.b16 {%0,%1,%2,%3}, [%4];"
        : "=r"(r[0]), "=r"(r[1]), "=r"(r[2]), "=r"(r[3]) : "r"(addr));
}
__device__ __forceinline__ void mma_bf16(float* d, const uint32_t* a, const uint32_t* b) {
    asm volatile("mma.sync.aligned.m16n8k16.row.col.f32.bf16.bf16.f32 "
        "{%0,%1,%2,%3}, {%4,%5,%6,%7}, {%8,%9}, {%0,%1,%2,%3};"
        : "+f"(d[0]), "+f"(d[1]), "+f"(d[2]), "+f"(d[3])
        : "r"(a[0]), "r"(a[1]), "r"(a[2]), "r"(a[3]), "r"(b[0]), "r"(b[1]));
}
__device__ __forceinline__ uint32_t bfhi2(float a, float b) {
    return __byte_perm(__float_as_uint(a), __float_as_uint(b), 0x7632);
}
__device__ __forceinline__ uint32_t bflo2(float a, float b) {
    const float la = a - __uint_as_float(__float_as_uint(a) & 0xFFFF0000u);
    const float lb = b - __uint_as_float(__float_as_uint(b) & 0xFFFF0000u);
    __nv_bfloat162 p = __floats2bfloat162_rn(la, lb);
    return *(uint32_t*)&p;
}
#define CP16(dst, src) asm volatile("cp.async.cg.shared.global [%0], [%1], 16;" :: "r"(dst), "l"(src))
#define CPCOMMIT()     asm volatile("cp.async.commit_group;" ::: "memory")
#define CPWAIT(n)      asm volatile("cp.async.wait_group %0;" :: "n"(n) : "memory")

// device scratch
__device__ float    g_interp[(size_t)Bn * C2n * Nn];
__device__ uint16_t g_p2h[(size_t)Bn * C2n * Mn];
__device__ uint16_t g_p2l[(size_t)Bn * C2n * Mn];
__device__ unsigned g_ord_i[512];   // per-SM arrival counters (parity used; no reset needed)
__device__ unsigned g_ord_m[512];

// CTA phase stagger: 2nd CTA arriving on an SM sleeps ~half a chunk period so
// co-resident CTAs run anti-phase (one's MMA covers the other's fill).
__device__ __forceinline__ void stagger(unsigned* ctr, unsigned ns, uint32_t* s_tmp) {
    if (threadIdx.x == 0) {
        uint32_t smid;
        asm("mov.u32 %0, %%smid;" : "=r"(smid));
        *s_tmp = atomicAdd(&ctr[smid & 511], 1u) & 1u;
    }
    __syncthreads();
    if (*s_tmp) __nanosleep(ns);
    __syncthreads();
}

// prep: split p2 fp32 -> bf16 hi/lo
__global__ void split_p2(const float* __restrict__ src)
{
    const size_t i = (size_t)blockIdx.x * 256 + threadIdx.x;   // float4 index
    const float4 v = ((const float4*)src)[i];
    uint2 h, l;
    h.x = bfhi2(v.x, v.y); h.y = bfhi2(v.z, v.w);
    l.x = bflo2(v.x, v.y); l.y = bflo2(v.z, v.w);
    ((uint2*)g_p2h)[i] = h;
    ((uint2*)g_p2l)[i] = l;
}

// paired-row address: two logical 64B rows per 144B physical row (conflict-free ldsm)
#define PR(r) (((r) >> 1) * 144 + ((r) & 1) * 64)

// ================= Kernel 1: interpolation via mma.sync =================
// CTA: 64 n x 256 c.  K = M = 1024 in 32-chunks, double-buffered, occ 2.
#define IA(buf, part)  ((buf) * 10240 + (part) * 5120)
#define IB(buf, part)  (20480 + (buf) * 36864 + (part) * 18432)
#define IOFF_X2  94208              // SoA: x[1024], y[1024], z[1024]
#define IOFF_DS  106496
#define IOFF_DEN 107520
#define IOFF_TMP 107776
#define ISMB     107792

__global__ __launch_bounds__(256, 2)
void interp_tc(const float* __restrict__ xyz1,
               const float* __restrict__ xyz2)
{
    extern __shared__ char smc[];
    const uint32_t sb = smem_u32(smc);
    float* s_x2x = (float*)(smc + IOFF_X2);
    float* s_x2y = s_x2x + Mn;
    float* s_x2z = s_x2x + 2 * Mn;
    float* s_ds  = (float*)(smc + IOFF_DS);
    float* s_den = (float*)(smc + IOFF_DEN);

    const int tid = threadIdx.x, w = tid >> 5, lane = tid & 31;
    const int b = blockIdx.y, n0 = blockIdx.x * 64;

    // xyz2 -> SoA smem
    for (int m = tid; m < Mn; m += 256) {
        const float3 v = ((const float3*)(xyz2 + (size_t)b * Mn * 3))[m];
        s_x2x[m] = v.x; s_x2y[m] = v.y; s_x2z[m] = v.z;
    }
    stagger(g_ord_i, 1300, (uint32_t*)(smc + IOFF_TMP));   // includes __syncthreads

    const int nf = tid & 63;
    const int g  = tid >> 6;
    const float px = xyz1[((size_t)b * Nn + n0 + nf) * 3 + 0];
    const float py = xyz1[((size_t)b * Nn + n0 + nf) * 3 + 1];
    const float pz = xyz1[((size_t)b * Nn + n0 + nf) * 3 + 2];
    float dsum = 0.f;

    const int mw = w & 1, cw = w >> 1;   // warp tile: 32 n x 64 c
    float acc[16][4];
    #pragma unroll
    for (int i = 0; i < 16; i++)
        #pragma unroll
        for (int j = 0; j < 4; j++) acc[i][j] = 0.f;

    const size_t p2base = (size_t)b * C2n * Mn;

    // A fill: SIMT rsqrt weights hi/lo (8 m per thread per chunk)
    #define FILLA(ch) do {                                                         \
        const int _buf = (ch) & 1, _mb = (ch) * 32 + g * 8;                        \
        const float4 xa = *(const float4*)&s_x2x[_mb];                             \
        const float4 xbv = *(const float4*)&s_x2x[_mb + 4];                        \
        const float4 ya = *(const float4*)&s_x2y[_mb];                             \
        const float4 yb = *(const float4*)&s_x2y[_mb + 4];                         \
        const float4 za = *(const float4*)&s_x2z[_mb];                             \
        const float4 zb = *(const float4*)&s_x2z[_mb + 4];                         \
        const float xs[8] = {xa.x, xa.y, xa.z, xa.w, xbv.x, xbv.y, xbv.z, xbv.w};  \
        const float ys[8] = {ya.x, ya.y, ya.z, ya.w, yb.x, yb.y, yb.z, yb.w};      \
        const float zs[8] = {za.x, za.y, za.z, za.w, zb.x, zb.y, zb.z, zb.w};      \
        float iv[8];                                                               \
        _Pragma("unroll")                                                          \
        for (int t = 0; t < 8; t++) {                                              \
            const float dx = px - xs[t];                                           \
            const float dy = py - ys[t];                                           \
            const float dz = pz - zs[t];                                           \
            const float d2 = fmaf(dx, dx, fmaf(dy, dy, fmaf(dz, dz, 1e-16f)));     \
            iv[t] = rsqrtf(d2);                                                    \
            dsum += iv[t];                                                         \
        }                                                                          \
        uint4 hv, lv;                                                              \
        hv.x = bfhi2(iv[0], iv[1]); hv.y = bfhi2(iv[2], iv[3]);                    \
        hv.z = bfhi2(iv[4], iv[5]); hv.w = bfhi2(iv[6], iv[7]);                    \
        lv.x = bflo2(iv[0], iv[1]); lv.y = bflo2(iv[2], iv[3]);                    \
        lv.z = bflo2(iv[4], iv[5]); lv.w = bflo2(iv[6], iv[7]);                    \
        *(uint4*)(smc + IA(_buf, 0) + nf * 80 + g * 16) = hv;                      \
        *(uint4*)(smc + IA(_buf, 1) + nf * 80 + g * 16) = lv;                      \
    } while (0)

    // B fill: cp.async pre-split p2 chunk, 8 x 16B per thread
    #define FILLB(ch) do {                                                         \
        const int _buf = (ch) & 1, _m0 = (ch) * 32;                                \
        _Pragma("unroll")                                                          \
        for (int it = 0; it < 8; it++) {                                           \
            const int u = tid + it * 256;                                          \
            const int part = u >> 10;                                              \
            const int v = u & 1023, c = v >> 2, s = v & 3;                         \
            const uint32_t dst = sb + IB(_buf, part) + PR(c) + s * 16;             \
            const uint16_t* srcp = part ? g_p2l : g_p2h;                           \
            CP16(dst, srcp + p2base + (size_t)c * Mn + _m0 + s * 8);               \
        }                                                                          \
        CPCOMMIT();                                                                \
    } while (0)

    FILLA(0);
    FILLB(0);

    for (int ch = 0; ch < 32; ch++) {
        const int buf = ch & 1;
        CPWAIT(0);
        __syncthreads();
        if (ch < 31) { FILLB(ch + 1); FILLA(ch + 1); }

        #pragma unroll
        for (int kk = 0; kk < 2; kk++) {
            uint32_t ah[2][4], al[2][4];
            #pragma unroll
            for (int mt = 0; mt < 2; mt++) {
                const uint32_t row = mw * 32 + mt * 16 + (lane & 15);
                const uint32_t off = row * 80 + kk * 32 + (lane >> 4) * 16;
                ldsm4(ah[mt], sb + IA(buf, 0) + off);
                ldsm4(al[mt], sb + IA(buf, 1) + off);
            }
            #pragma unroll
            for (int cp = 0; cp < 4; cp++) {
                const uint32_t c = cw * 64 + cp * 16 + (lane >> 4) * 8 + (lane & 7);
                const uint32_t off = PR(c) + kk * 32 + ((lane >> 3) & 1) * 16;
                uint32_t rh[4], rl[4];
                ldsm4(rh, sb + IB(buf, 0) + off);
                ldsm4(rl, sb + IB(buf, 1) + off);
                #pragma unroll
                for (int mt = 0; mt < 2; mt++) {
                    mma_bf16(acc[mt * 8 + cp * 2],     ah[mt], rh);
                    mma_bf16(acc[mt * 8 + cp * 2 + 1], ah[mt], rh + 2);
                    mma_bf16(acc[mt * 8 + cp * 2],     ah[mt], rl);
                    mma_bf16(acc[mt * 8 + cp * 2 + 1], ah[mt], rl + 2);
                    mma_bf16(acc[mt * 8 + cp * 2],     al[mt], rh);
                    mma_bf16(acc[mt * 8 + cp * 2 + 1], al[mt], rh + 2);
                }
            }
        }
    }
    #undef FILLA
    #undef FILLB

    // denominator
    __syncthreads();
    s_ds[tid] = dsum;
    __syncthreads();
    if (tid < 64)
        s_den[tid] = 1.0f / (s_ds[tid] + s_ds[tid + 64] + s_ds[tid + 128] + s_ds[tid + 192]);
    __syncthreads();

    // epilogue: scale and store
    #pragma unroll
    for (int mt = 0; mt < 2; mt++) {
        const int nl = mw * 32 + mt * 16 + (lane >> 2);
        const float i0 = s_den[nl], i1 = s_den[nl + 8];
        #pragma unroll
        for (int ct = 0; ct < 8; ct++) {
            const int c = cw * 64 + ct * 8 + (lane & 3) * 2;
            float* d0 = &g_interp[((size_t)b * C2n + c) * Nn + n0];
            float* d1 = &g_interp[((size_t)b * C2n + c + 1) * Nn + n0];
            const float* a = acc[mt * 8 + ct];
            d0[nl]     = a[0] * i0;
            d1[nl]     = a[1] * i0;
            d0[nl + 8] = a[2] * i1;
            d1[nl + 8] = a[3] * i1;
        }
    }
}

// ================= Kernel 2: fused 2-layer MLP via mma.sync =================
#define MW(buf, part)   ((buf) * 36864 + (part) * 18432)          // W1 chunk [256o][32k] paired
#define MH(part)        ((part) * 36864)                           // h [256k][64n] (overlays MW)
#define MX(buf, part)   (73728 + (buf) * 9216 + (part) * 4608)     // x chunk [32k][64n]
#define MW2(buf, part)  (73728 + (buf) * 18432 + (part) * 9216)    // W2 chunk [128o][32k] paired
#define MOFF_B1  110592
#define MOFF_B2  111616
#define MOFF_TMP 112128
#define MSMB     112144

__global__ __launch_bounds__(256, 2)
void mlp_tc(const float* __restrict__ p1,
            const float* __restrict__ W1,
            const float* __restrict__ b1,
            const float* __restrict__ W2,
            const float* __restrict__ b2,
            float* __restrict__ out)
{
    extern __shared__ char smc[];
    const uint32_t sb = smem_u32(smc);
    float* s_b1 = (float*)(smc + MOFF_B1);
    float* s_b2 = (float*)(smc + MOFF_B2);

    const int tid = threadIdx.x, w = tid >> 5, lane = tid & 31;
    const int b = blockIdx.y, n0 = blockIdx.x * 64;

    s_b1[tid] = b1[tid];
    if (tid < H2n) s_b2[tid] = b2[tid];

    stagger(g_ord_m, 1100, (uint32_t*)(smc + MOFF_TMP));

    const int ow = w >> 1, nw = w & 1;   // GEMM1 warp: 64 o x 32 n

    #define FILLW1(kc) do {                                                         \
        const int _buf = (kc) & 1;                                                  \
        _Pragma("unroll")                                                           \
        for (int it = 0; it < 8; it++) {                                            \
            const int u = tid + it * 256;                                           \
            const int o = u >> 3, q = u & 7;                                        \
            const float4 v = *(const float4*)&W1[(size_t)o * CINn + (kc) * 32 + q * 4]; \
            uint2 hv, lv;                                                           \
            hv.x = bfhi2(v.x, v.y); hv.y = bfhi2(v.z, v.w);                         \
            lv.x = bflo2(v.x, v.y); lv.y = bflo2(v.z, v.w);                         \
            *(uint2*)(smc + MW(_buf, 0) + PR(o) + q * 8) = hv;                      \
            *(uint2*)(smc + MW(_buf, 1) + PR(o) + q * 8) = lv;                      \
        }                                                                           \
    } while (0)

    #define FILLX(kc) do {                                                          \
        const int _buf = (kc) & 1;                                                  \
        _Pragma("unroll")                                                           \
        for (int it = 0; it < 2; it++) {                                            \
            const int u = tid + it * 256;                                           \
            const int k = u >> 4, q = u & 15;                                       \
            const int c = (kc) * 32 + k;                                            \
            const float* src = (c < C1n)                                            \
                ? &p1[((size_t)b * C1n + c) * Nn]                                   \
                : &g_interp[((size_t)b * C2n + (c - C1n)) * Nn];                    \
            const float4 v = *(const float4*)&src[n0 + q * 4];                      \
            uint2 hv, lv;                                                           \
            hv.x = bfhi2(v.x, v.y); hv.y = bfhi2(v.z, v.w);                         \
            lv.x = bflo2(v.x, v.y); lv.y = bflo2(v.z, v.w);                         \
            *(uint2*)(smc + MX(_buf, 0) + k * 144 + q * 8) = hv;                    \
            *(uint2*)(smc + MX(_buf, 1) + k * 144 + q * 8) = lv;                    \
        }                                                                           \
    } while (0)

    float acc1[16][4];
    #pragma unroll
    for (int i = 0; i < 16; i++)
        #pragma unroll
        for (int j = 0; j < 4; j++) acc1[i][j] = 0.f;

    FILLW1(0); FILLX(0);
    __syncthreads();

    for (int kc = 0; kc < 12; kc++) {
        const int buf = kc & 1;
        #pragma unroll
        for (int kk = 0; kk < 2; kk++) {
            uint32_t wh[4][4], wl[4][4];
            #pragma unroll
            for (int mi = 0; mi < 4; mi++) {
                const uint32_t o = ow * 64 + mi * 16 + (lane & 15);
                const uint32_t off = PR(o) + kk * 32 + (lane >> 4) * 16;
                ldsm4(wh[mi], sb + MW(buf, 0) + off);
                ldsm4(wl[mi], sb + MW(buf, 1) + off);
            }
            uint32_t xh[4][2], xl[4][2];
            #pragma unroll
            for (int np = 0; np < 2; np++) {
                const uint32_t row  = kk * 16 + ((lane >> 3) & 1) * 8 + (lane & 7);
                const uint32_t colb = (nw * 32 + np * 16) * 2 + (lane >> 4) * 16;
                uint32_t r[4];
                ldsm4t(r, sb + MX(buf, 0) + row * 144 + colb);
                xh[np * 2][0] = r[0]; xh[np * 2][1] = r[1];
                xh[np * 2 + 1][0] = r[2]; xh[np * 2 + 1][1] = r[3];
                ldsm4t(r, sb + MX(buf, 1) + row * 144 + colb);
                xl[np * 2][0] = r[0]; xl[np * 2][1] = r[1];
                xl[np * 2 + 1][0] = r[2]; xl[np * 2 + 1][1] = r[3];
            }
            #pragma unroll
            for (int mi = 0; mi < 4; mi++)
                #pragma unroll
                for (int ni = 0; ni < 4; ni++) {
                    mma_bf16(acc1[mi * 4 + ni], wh[mi], xh[ni]);
                    mma_bf16(acc1[mi * 4 + ni], wh[mi], xl[ni]);
                    mma_bf16(acc1[mi * 4 + ni], wl[mi], xh[ni]);
                }
        }
        if (kc < 11) { FILLW1(kc + 1); FILLX(kc + 1); }
        __syncthreads();
    }
    #undef FILLW1
    #undef FILLX

    #define FILLW2(kc) do {                                                         \
        const int _buf = (kc) & 1;                                                  \
        _Pragma("unroll")                                                           \
        for (int it = 0; it < 4; it++) {                                            \
            const int u = tid + it * 256;                                           \
            const int o = u >> 3, q = u & 7;                                        \
            const float4 v = *(const float4*)&W2[(size_t)o * H1n + (kc) * 32 + q * 4]; \
            uint2 hv, lv;                                                           \
            hv.x = bfhi2(v.x, v.y); hv.y = bfhi2(v.z, v.w);                         \
            lv.x = bflo2(v.x, v.y); lv.y = bflo2(v.z, v.w);                         \
            *(uint2*)(smc + MW2(_buf, 0) + PR(o) + q * 8) = hv;                     \
            *(uint2*)(smc + MW2(_buf, 1) + PR(o) + q * 8) = lv;                     \
        }                                                                           \
    } while (0)

    // W1/x regions fully read; repurpose for W2 + h
    FILLW2(0);

    // GEMM1 epilogue: relu + bias -> s_h [256 k-rows][64 n], hi/lo (overlays MW)
    #pragma unroll
    for (int mi = 0; mi < 4; mi++) {
        const int o = ow * 64 + mi * 16 + (lane >> 2);
        const float bia0 = s_b1[o], bia1 = s_b1[o + 8];
        #pragma unroll
        for (int ni = 0; ni < 4; ni++) {
            const int n = nw * 32 + ni * 8 + (lane & 3) * 2;
            const float* a = acc1[mi * 4 + ni];
            const float v0 = fmaxf(a[0] + bia0, 0.f);
            const float v1 = fmaxf(a[1] + bia0, 0.f);
            const float v2 = fmaxf(a[2] + bia1, 0.f);
            const float v3 = fmaxf(a[3] + bia1, 0.f);
            *(uint32_t*)(smc + MH(0) + o * 144 + n * 2)       = bfhi2(v0, v1);
            *(uint32_t*)(smc + MH(1) + o * 144 + n * 2)       = bflo2(v0, v1);
            *(uint32_t*)(smc + MH(0) + (o + 8) * 144 + n * 2) = bfhi2(v2, v3);
            *(uint32_t*)(smc + MH(1) + (o + 8) * 144 + n * 2) = bflo2(v2, v3);
        }
    }
    __syncthreads();

    // ---------- GEMM2 (distance-1 double buffer, race-free) ----------
    const int ow2 = w >> 1;   // 32 o per warp
    float acc2[8][4];
    #pragma unroll
    for (int i = 0; i < 8; i++)
        #pragma unroll
        for (int j = 0; j < 4; j++) acc2[i][j] = 0.f;

    for (int kc = 0; kc < 8; kc++) {
        const int buf = kc & 1;
        #pragma unroll
        for (int kk = 0; kk < 2; kk++) {
            uint32_t wh[2][4], wl[2][4];
            #pragma unroll
            for (int mi = 0; mi < 2; mi++) {
                const uint32_t o = ow2 * 32 + mi * 16 + (lane & 15);
                const uint32_t off = PR(o) + kk * 32 + (lane >> 4) * 16;
                ldsm4(wh[mi], sb + MW2(buf, 0) + off);
                ldsm4(wl[mi], sb + MW2(buf, 1) + off);
            }
            uint32_t hh[4][2], hl[4][2];
            #pragma unroll
            for (int np = 0; np < 2; np++) {
                const uint32_t row  = kc * 32 + kk * 16 + ((lane >> 3) & 1) * 8 + (lane & 7);
                const uint32_t colb = (nw * 32 + np * 16) * 2 + (lane >> 4) * 16;
                uint32_t r[4];
                ldsm4t(r, sb + MH(0) + row * 144 + colb);
                hh[np * 2][0] = r[0]; hh[np * 2][1] = r[1];
                hh[np * 2 + 1][0] = r[2]; hh[np * 2 + 1][1] = r[3];
                ldsm4t(r, sb + MH(1) + row * 144 + colb);
                hl[np * 2][0] = r[0]; hl[np * 2][1] = r[1];
                hl[np * 2 + 1][0] = r[2]; hl[np * 2 + 1][1] = r[3];
            }
            #pragma unroll
            for (int mi = 0; mi < 2; mi++)
                #pragma unroll
                for (int ni = 0; ni < 4; ni++) {
                    mma_bf16(acc2[mi * 4 + ni], wh[mi], hh[ni]);
                    mma_bf16(acc2[mi * 4 + ni], wh[mi], hl[ni]);
                    mma_bf16(acc2[mi * 4 + ni], wl[mi], hh[ni]);
                }
        }
        if (kc < 7) FILLW2(kc + 1);   // writes OTHER buffer — safe
        __syncthreads();
    }
    #undef FILLW2

    // ---------- output ----------
    #pragma unroll
    for (int mi = 0; mi < 2; mi++) {
        const int o = ow2 * 32 + mi * 16 + (lane >> 2);
        const float bia0 = s_b2[o], bia1 = s_b2[o + 8];
        #pragma unroll
        for (int ni = 0; ni < 4; ni++) {
            const int n = n0 + nw * 32 + ni * 8 + (lane & 3) * 2;
            const float* a = acc2[mi * 4 + ni];
            float2 v0, v1;
            v0.x = fmaxf(a[0] + bia0, 0.f);
            v0.y = fmaxf(a[1] + bia0, 0.f);
            v1.x = fmaxf(a[2] + bia1, 0.f);
            v1.y = fmaxf(a[3] + bia1, 0.f);
            *(float2*)&out[((size_t)b * H2n + o) * Nn + n]     = v0;
            *(float2*)&out[((size_t)b * H2n + o + 8) * Nn + n] = v1;
        }
    }
}

extern "C" void kernel_launch(void* const* d_in, const int* in_sizes, int n_in,
                              void* d_out, int out_size)
{
    const float* xyz1 = (const float*)d_in[0];
    const float* xyz2 = (const float*)d_in[1];
    const float* p1   = (const float*)d_in[2];
    const float* p2   = (const float*)d_in[3];
    const float* W1   = (const float*)d_in[4];
    const float* b1   = (const float*)d_in[5];
    const float* W2   = (const float*)d_in[6];
    const float* b2   = (const float*)d_in[7];
    float* out = (float*)d_out;

    cudaFuncSetAttribute(interp_tc, cudaFuncAttributeMaxDynamicSharedMemorySize, ISMB);
    cudaFuncSetAttribute(mlp_tc,    cudaFuncAttributeMaxDynamicSharedMemorySize, MSMB);

    split_p2<<<(Bn * C2n * Mn / 4) / 256, 256>>>(p2);
    dim3 grid(Nn / 64, Bn);
    interp_tc<<<grid, 256, ISMB>>>(xyz1, xyz2);
    mlp_tc<<<grid, 256, MSMB>>>(p1, W1, b1, W2, b2, out);
}

// round 11
// speedup vs baseline: 1.5199x; 1.3790x over previous
#include <cuda_runtime.h>
#include <cuda_fp16.h>
#include <cstdint>

// Problem constants
#define Bn   16
#define Nn   4096
#define Mn   1024
#define C1n  128
#define C2n  256
#define CINn 384
#define H1n  256
#define H2n  128

#define WSCALE 0.00048828125f   // 2^-11: keeps inv-dist weights < fp16 max; cancels in ratio

// ---------------- helpers ----------------
__device__ __forceinline__ uint32_t smem_u32(const void* p) {
    uint32_t a;
    asm("{ .reg .u64 t; cvta.to.shared.u64 t, %1; cvt.u32.u64 %0, t; }" : "=r"(a) : "l"(p));
    return a;
}
__device__ __forceinline__ void ldsm4(uint32_t* r, uint32_t addr) {
    asm volatile("ldmatrix.sync.aligned.m8n8.x4.shared.b16 {%0,%1,%2,%3}, [%4];"
        : "=r"(r[0]), "=r"(r[1]), "=r"(r[2]), "=r"(r[3]) : "r"(addr));
}
__device__ __forceinline__ void ldsm4t(uint32_t* r, uint32_t addr) {
    asm volatile("ldmatrix.sync.aligned.m8n8.x4.trans.shared.b16 {%0,%1,%2,%3}, [%4];"
        : "=r"(r[0]), "=r"(r[1]), "=r"(r[2]), "=r"(r[3]) : "r"(addr));
}
__device__ __forceinline__ void mma_f16(float* d, const uint32_t* a, const uint32_t* b) {
    asm volatile("mma.sync.aligned.m16n8k16.row.col.f32.f16.f16.f32 "
        "{%0,%1,%2,%3}, {%4,%5,%6,%7}, {%8,%9}, {%0,%1,%2,%3};"
        : "+f"(d[0]), "+f"(d[1]), "+f"(d[2]), "+f"(d[3])
        : "r"(a[0]), "r"(a[1]), "r"(a[2]), "r"(a[3]), "r"(b[0]), "r"(b[1]));
}
// fp16 pack of two floats (rn)
__device__ __forceinline__ uint32_t h2pack(float a, float b) {
    __half2 h = __floats2half2_rn(a, b);
    return *(uint32_t*)&h;
}
// fp16 two-term split of a float pair: hi = rn(x), lo = rn(x - hi)
__device__ __forceinline__ void hsplit2(float a, float b, uint32_t& hi, uint32_t& lo) {
    __half2 h = __floats2half2_rn(a, b);
    float2 hf = __half22float2(h);
    __half2 l = __floats2half2_rn(a - hf.x, b - hf.y);
    hi = *(uint32_t*)&h;
    lo = *(uint32_t*)&l;
}
#define CP16(dst, src) asm volatile("cp.async.cg.shared.global [%0], [%1], 16;" :: "r"(dst), "l"(src))
#define CPCOMMIT()     asm volatile("cp.async.commit_group;" ::: "memory")
#define CPWAIT(n)      asm volatile("cp.async.wait_group %0;" :: "n"(n) : "memory")

// device scratch
__device__ float    g_interp[(size_t)Bn * C2n * Nn];
__device__ uint16_t g_p2f[(size_t)Bn * C2n * Mn];   // p2 as fp16

// prep: p2 fp32 -> fp16
__global__ void split_p2f(const float* __restrict__ src)
{
    const size_t i = (size_t)blockIdx.x * 256 + threadIdx.x;   // float4 index
    const float4 v = ((const float4*)src)[i];
    uint2 o;
    o.x = h2pack(v.x, v.y);
    o.y = h2pack(v.z, v.w);
    ((uint2*)g_p2f)[i] = o;
}

// paired-row address: two logical 64B rows per 144B physical row (conflict-free ldsm)
#define PR(r) (((r) >> 1) * 144 + ((r) & 1) * 64)

// ================= Kernel 1: interpolation via mma.sync (fp16, 2-pass) =================
// CTA: 64 n x 256 c.  K = M = 1024 in 32-chunks, double-buffered, occ 2.
// A [64n][32k] hi/lo fp16, pitch 80 (SIMT fill); B [256c][32k] single fp16 (cp.async).
#define IA(buf, part)  ((buf) * 10240 + (part) * 5120)
#define IB(buf)        (20480 + (buf) * 18432)
#define IOFF_X2  57344              // SoA: x[1024], y[1024], z[1024]
#define IOFF_DS  69632
#define IOFF_DEN 70656
#define ISMB     70912

__global__ __launch_bounds__(256, 2)
void interp_tc(const float* __restrict__ xyz1,
               const float* __restrict__ xyz2)
{
    extern __shared__ char smc[];
    const uint32_t sb = smem_u32(smc);
    float* s_x2x = (float*)(smc + IOFF_X2);
    float* s_x2y = s_x2x + Mn;
    float* s_x2z = s_x2x + 2 * Mn;
    float* s_ds  = (float*)(smc + IOFF_DS);
    float* s_den = (float*)(smc + IOFF_DEN);

    const int tid = threadIdx.x, w = tid >> 5, lane = tid & 31;
    const int b = blockIdx.y, n0 = blockIdx.x * 64;

    // xyz2 -> SoA smem
    for (int m = tid; m < Mn; m += 256) {
        const float3 v = ((const float3*)(xyz2 + (size_t)b * Mn * 3))[m];
        s_x2x[m] = v.x; s_x2y[m] = v.y; s_x2z[m] = v.z;
    }
    __syncthreads();

    const int nf = tid & 63;        // point this thread generates weights for
    const int g  = tid >> 6;        // 8-m group within 32-chunk
    const float px = xyz1[((size_t)b * Nn + n0 + nf) * 3 + 0];
    const float py = xyz1[((size_t)b * Nn + n0 + nf) * 3 + 1];
    const float pz = xyz1[((size_t)b * Nn + n0 + nf) * 3 + 2];
    float dsum = 0.f;               // accumulates SCALED weights; cancels in ratio

    const int mw = w & 1, cw = w >> 1;   // warp tile: 32 n x 64 c
    float acc[16][4];
    #pragma unroll
    for (int i = 0; i < 16; i++)
        #pragma unroll
        for (int j = 0; j < 4; j++) acc[i][j] = 0.f;

    const size_t p2base = (size_t)b * C2n * Mn;

    // A fill: rsqrt weights (scaled) -> fp16 hi/lo
    #define FILLA(ch) do {                                                         \
        const int _buf = (ch) & 1, _mb = (ch) * 32 + g * 8;                        \
        const float4 xa = *(const float4*)&s_x2x[_mb];                             \
        const float4 xbv = *(const float4*)&s_x2x[_mb + 4];                        \
        const float4 ya = *(const float4*)&s_x2y[_mb];                             \
        const float4 yb = *(const float4*)&s_x2y[_mb + 4];                         \
        const float4 za = *(const float4*)&s_x2z[_mb];                             \
        const float4 zb = *(const float4*)&s_x2z[_mb + 4];                         \
        const float xs[8] = {xa.x, xa.y, xa.z, xa.w, xbv.x, xbv.y, xbv.z, xbv.w};  \
        const float ys[8] = {ya.x, ya.y, ya.z, ya.w, yb.x, yb.y, yb.z, yb.w};      \
        const float zs[8] = {za.x, za.y, za.z, za.w, zb.x, zb.y, zb.z, zb.w};      \
        float iv[8];                                                               \
        _Pragma("unroll")                                                          \
        for (int t = 0; t < 8; t++) {                                              \
            const float dx = px - xs[t];                                           \
            const float dy = py - ys[t];                                           \
            const float dz = pz - zs[t];                                           \
            const float d2 = fmaf(dx, dx, fmaf(dy, dy, fmaf(dz, dz, 1e-16f)));     \
            iv[t] = rsqrtf(d2) * WSCALE;                                           \
            dsum += iv[t];                                                         \
        }                                                                          \
        uint4 hv, lv;                                                              \
        hsplit2(iv[0], iv[1], hv.x, lv.x);                                         \
        hsplit2(iv[2], iv[3], hv.y, lv.y);                                         \
        hsplit2(iv[4], iv[5], hv.z, lv.z);                                         \
        hsplit2(iv[6], iv[7], hv.w, lv.w);                                         \
        *(uint4*)(smc + IA(_buf, 0) + nf * 80 + g * 16) = hv;                      \
        *(uint4*)(smc + IA(_buf, 1) + nf * 80 + g * 16) = lv;                      \
    } while (0)

    // B fill: cp.async fp16 p2 chunk, 4 x 16B per thread
    #define FILLB(ch) do {                                                         \
        const int _buf = (ch) & 1, _m0 = (ch) * 32;                                \
        _Pragma("unroll")                                                          \
        for (int it = 0; it < 4; it++) {                                           \
            const int u = tid + it * 256;                                          \
            const int c = u >> 2, s = u & 3;                                       \
            const uint32_t dst = sb + IB(_buf) + PR(c) + s * 16;                   \
            CP16(dst, g_p2f + p2base + (size_t)c * Mn + _m0 + s * 8);              \
        }                                                                          \
        CPCOMMIT();                                                                \
    } while (0)

    FILLA(0);
    FILLB(0);

    for (int ch = 0; ch < 32; ch++) {
        const int buf = ch & 1;
        CPWAIT(0);
        __syncthreads();
        if (ch < 31) { FILLB(ch + 1); FILLA(ch + 1); }

        #pragma unroll
        for (int kk = 0; kk < 2; kk++) {
            uint32_t ah[2][4], al[2][4];
            #pragma unroll
            for (int mt = 0; mt < 2; mt++) {
                const uint32_t row = mw * 32 + mt * 16 + (lane & 15);
                const uint32_t off = row * 80 + kk * 32 + (lane >> 4) * 16;
                ldsm4(ah[mt], sb + IA(buf, 0) + off);
                ldsm4(al[mt], sb + IA(buf, 1) + off);
            }
            #pragma unroll
            for (int cp = 0; cp < 4; cp++) {
                const uint32_t c = cw * 64 + cp * 16 + (lane >> 4) * 8 + (lane & 7);
                const uint32_t off = PR(c) + kk * 32 + ((lane >> 3) & 1) * 16;
                uint32_t rh[4];
                ldsm4(rh, sb + IB(buf) + off);
                #pragma unroll
                for (int mt = 0; mt < 2; mt++) {
                    mma_f16(acc[mt * 8 + cp * 2],     ah[mt], rh);
                    mma_f16(acc[mt * 8 + cp * 2 + 1], ah[mt], rh + 2);
                    mma_f16(acc[mt * 8 + cp * 2],     al[mt], rh);
                    mma_f16(acc[mt * 8 + cp * 2 + 1], al[mt], rh + 2);
                }
            }
        }
    }
    #undef FILLA
    #undef FILLB

    // denominator (scaled; cancels with scaled numerator)
    __syncthreads();
    s_ds[tid] = dsum;
    __syncthreads();
    if (tid < 64)
        s_den[tid] = 1.0f / (s_ds[tid] + s_ds[tid + 64] + s_ds[tid + 128] + s_ds[tid + 192]);
    __syncthreads();

    // epilogue: scale and store
    #pragma unroll
    for (int mt = 0; mt < 2; mt++) {
        const int nl = mw * 32 + mt * 16 + (lane >> 2);
        const float i0 = s_den[nl], i1 = s_den[nl + 8];
        #pragma unroll
        for (int ct = 0; ct < 8; ct++) {
            const int c = cw * 64 + ct * 8 + (lane & 3) * 2;
            float* d0 = &g_interp[((size_t)b * C2n + c) * Nn + n0];
            float* d1 = &g_interp[((size_t)b * C2n + c + 1) * Nn + n0];
            const float* a = acc[mt * 8 + ct];
            d0[nl]     = a[0] * i0;
            d1[nl]     = a[1] * i0;
            d0[nl + 8] = a[2] * i1;
            d1[nl + 8] = a[3] * i1;
        }
    }
}

// ================= Kernel 2: fused 2-layer MLP (fp16, 2-pass) =================
// CTA: 64 n. GEMM1: 256o x 64n x K384 (32-chunks); GEMM2: 128o x 64n x K256.
// Weights split fp16 hi/lo; activations single fp16.
#define MW(buf, part)   ((buf) * 36864 + (part) * 18432)           // W1 chunk [256o][32k] paired
#define MH              0                                           // h [256k][64n] single fp16 (overlays MW buf0)
#define MW2(buf, part)  (36864 + (buf) * 18432 + (part) * 9216)     // W2 chunk [128o][32k] paired (overlays MW buf1)
#define MX(buf)         (73728 + (buf) * 4608)                      // x chunk [32k][64n] single fp16
#define MOFF_B1  82944
#define MOFF_B2  83968
#define MSMB     84480

__global__ __launch_bounds__(256, 2)
void mlp_tc(const float* __restrict__ p1,
            const float* __restrict__ W1,
            const float* __restrict__ b1,
            const float* __restrict__ W2,
            const float* __restrict__ b2,
            float* __restrict__ out)
{
    extern __shared__ char smc[];
    const uint32_t sb = smem_u32(smc);
    float* s_b1 = (float*)(smc + MOFF_B1);
    float* s_b2 = (float*)(smc + MOFF_B2);

    const int tid = threadIdx.x, w = tid >> 5, lane = tid & 31;
    const int b = blockIdx.y, n0 = blockIdx.x * 64;

    s_b1[tid] = b1[tid];
    if (tid < H2n) s_b2[tid] = b2[tid];

    const int ow = w >> 1, nw = w & 1;   // GEMM1 warp: 64 o x 32 n

    #define FILLW1(kc) do {                                                         \
        const int _buf = (kc) & 1;                                                  \
        _Pragma("unroll")                                                           \
        for (int it = 0; it < 8; it++) {                                            \
            const int u = tid + it * 256;                                           \
            const int o = u >> 3, q = u & 7;                                        \
            const float4 v = *(const float4*)&W1[(size_t)o * CINn + (kc) * 32 + q * 4]; \
            uint2 hv, lv;                                                           \
            hsplit2(v.x, v.y, hv.x, lv.x);                                          \
            hsplit2(v.z, v.w, hv.y, lv.y);                                          \
            *(uint2*)(smc + MW(_buf, 0) + PR(o) + q * 8) = hv;                      \
            *(uint2*)(smc + MW(_buf, 1) + PR(o) + q * 8) = lv;                      \
        }                                                                           \
    } while (0)

    #define FILLX(kc) do {                                                          \
        const int _buf = (kc) & 1;                                                  \
        const int k = tid >> 3, q = tid & 7;                                        \
        const int c = (kc) * 32 + k;                                                \
        const float* src = (c < C1n)                                                \
            ? &p1[((size_t)b * C1n + c) * Nn]                                       \
            : &g_interp[((size_t)b * C2n + (c - C1n)) * Nn];                        \
        const float4 v0 = *(const float4*)&src[n0 + q * 8];                         \
        const float4 v1 = *(const float4*)&src[n0 + q * 8 + 4];                     \
        uint4 xv;                                                                   \
        xv.x = h2pack(v0.x, v0.y); xv.y = h2pack(v0.z, v0.w);                       \
        xv.z = h2pack(v1.x, v1.y); xv.w = h2pack(v1.z, v1.w);                       \
        *(uint4*)(smc + MX(_buf) + k * 144 + q * 16) = xv;                          \
    } while (0)

    float acc1[16][4];
    #pragma unroll
    for (int i = 0; i < 16; i++)
        #pragma unroll
        for (int j = 0; j < 4; j++) acc1[i][j] = 0.f;

    FILLW1(0); FILLX(0);
    __syncthreads();

    for (int kc = 0; kc < 12; kc++) {
        const int buf = kc & 1;
        #pragma unroll
        for (int kk = 0; kk < 2; kk++) {
            uint32_t wh[4][4], wl[4][4];
            #pragma unroll
            for (int mi = 0; mi < 4; mi++) {
                const uint32_t o = ow * 64 + mi * 16 + (lane & 15);
                const uint32_t off = PR(o) + kk * 32 + (lane >> 4) * 16;
                ldsm4(wh[mi], sb + MW(buf, 0) + off);
                ldsm4(wl[mi], sb + MW(buf, 1) + off);
            }
            uint32_t xh[4][2];
            #pragma unroll
            for (int np = 0; np < 2; np++) {
                const uint32_t row  = kk * 16 + ((lane >> 3) & 1) * 8 + (lane & 7);
                const uint32_t colb = (nw * 32 + np * 16) * 2 + (lane >> 4) * 16;
                uint32_t r[4];
                ldsm4t(r, sb + MX(buf) + row * 144 + colb);
                xh[np * 2][0] = r[0]; xh[np * 2][1] = r[1];
                xh[np * 2 + 1][0] = r[2]; xh[np * 2 + 1][1] = r[3];
            }
            #pragma unroll
            for (int mi = 0; mi < 4; mi++)
                #pragma unroll
                for (int ni = 0; ni < 4; ni++) {
                    mma_f16(acc1[mi * 4 + ni], wh[mi], xh[ni]);
                    mma_f16(acc1[mi * 4 + ni], wl[mi], xh[ni]);
                }
        }
        if (kc < 11) { FILLW1(kc + 1); FILLX(kc + 1); }
        __syncthreads();
    }
    #undef FILLW1
    #undef FILLX

    #define FILLW2(kc) do {                                                         \
        const int _buf = (kc) & 1;                                                  \
        _Pragma("unroll")                                                           \
        for (int it = 0; it < 4; it++) {                                            \
            const int u = tid + it * 256;                                           \
            const int o = u >> 3, q = u & 7;                                        \
            const float4 v = *(const float4*)&W2[(size_t)o * H1n + (kc) * 32 + q * 4]; \
            uint2 hv, lv;                                                           \
            hsplit2(v.x, v.y, hv.x, lv.x);                                          \
            hsplit2(v.z, v.w, hv.y, lv.y);                                          \
            *(uint2*)(smc + MW2(_buf, 0) + PR(o) + q * 8) = hv;                     \
            *(uint2*)(smc + MW2(_buf, 1) + PR(o) + q * 8) = lv;                     \
        }                                                                           \
    } while (0)

    // W1/x regions fully read; repurpose for W2 + h
    FILLW2(0);

    // GEMM1 epilogue: relu + bias -> s_h [256 k-rows][64 n], single fp16 (overlays MW buf0)
    #pragma unroll
    for (int mi = 0; mi < 4; mi++) {
        const int o = ow * 64 + mi * 16 + (lane >> 2);
        const float bia0 = s_b1[o], bia1 = s_b1[o + 8];
        #pragma unroll
        for (int ni = 0; ni < 4; ni++) {
            const int n = nw * 32 + ni * 8 + (lane & 3) * 2;
            const float* a = acc1[mi * 4 + ni];
            const float v0 = fmaxf(a[0] + bia0, 0.f);
            const float v1 = fmaxf(a[1] + bia0, 0.f);
            const float v2 = fmaxf(a[2] + bia1, 0.f);
            const float v3 = fmaxf(a[3] + bia1, 0.f);
            *(uint32_t*)(smc + MH + o * 144 + n * 2)       = h2pack(v0, v1);
            *(uint32_t*)(smc + MH + (o + 8) * 144 + n * 2) = h2pack(v2, v3);
        }
    }
    __syncthreads();

    // ---------- GEMM2 (distance-1 double buffer) ----------
    const int ow2 = w >> 1;   // 32 o per warp
    float acc2[8][4];
    #pragma unroll
    for (int i = 0; i < 8; i++)
        #pragma unroll
        for (int j = 0; j < 4; j++) acc2[i][j] = 0.f;

    for (int kc = 0; kc < 8; kc++) {
        const int buf = kc & 1;
        #pragma unroll
        for (int kk = 0; kk < 2; kk++) {
            uint32_t wh[2][4], wl[2][4];
            #pragma unroll
            for (int mi = 0; mi < 2; mi++) {
                const uint32_t o = ow2 * 32 + mi * 16 + (lane & 15);
                const uint32_t off = PR(o) + kk * 32 + (lane >> 4) * 16;
                ldsm4(wh[mi], sb + MW2(buf, 0) + off);
                ldsm4(wl[mi], sb + MW2(buf, 1) + off);
            }
            uint32_t hh[4][2];
            #pragma unroll
            for (int np = 0; np < 2; np++) {
                const uint32_t row  = kc * 32 + kk * 16 + ((lane >> 3) & 1) * 8 + (lane & 7);
                const uint32_t colb = (nw * 32 + np * 16) * 2 + (lane >> 4) * 16;
                uint32_t r[4];
                ldsm4t(r, sb + MH + row * 144 + colb);
                hh[np * 2][0] = r[0]; hh[np * 2][1] = r[1];
                hh[np * 2 + 1][0] = r[2]; hh[np * 2 + 1][1] = r[3];
            }
            #pragma unroll
            for (int mi = 0; mi < 2; mi++)
                #pragma unroll
                for (int ni = 0; ni < 4; ni++) {
                    mma_f16(acc2[mi * 4 + ni], wh[mi], hh[ni]);
                    mma_f16(acc2[mi * 4 + ni], wl[mi], hh[ni]);
                }
        }
        if (kc < 7) FILLW2(kc + 1);   // writes OTHER buffer — safe
        __syncthreads();
    }
    #undef FILLW2

    // ---------- output ----------
    #pragma unroll
    for (int mi = 0; mi < 2; mi++) {
        const int o = ow2 * 32 + mi * 16 + (lane >> 2);
        const float bia0 = s_b2[o], bia1 = s_b2[o + 8];
        #pragma unroll
        for (int ni = 0; ni < 4; ni++) {
            const int n = n0 + nw * 32 + ni * 8 + (lane & 3) * 2;
            const float* a = acc2[mi * 4 + ni];
            float2 v0, v1;
            v0.x = fmaxf(a[0] + bia0, 0.f);
            v0.y = fmaxf(a[1] + bia0, 0.f);
            v1.x = fmaxf(a[2] + bia1, 0.f);
            v1.y = fmaxf(a[3] + bia1, 0.f);
            *(float2*)&out[((size_t)b * H2n + o) * Nn + n]     = v0;
            *(float2*)&out[((size_t)b * H2n + o + 8) * Nn + n] = v1;
        }
    }
}

extern "C" void kernel_launch(void* const* d_in, const int* in_sizes, int n_in,
                              void* d_out, int out_size)
{
    const float* xyz1 = (const float*)d_in[0];
    const float* xyz2 = (const float*)d_in[1];
    const float* p1   = (const float*)d_in[2];
    const float* p2   = (const float*)d_in[3];
    const float* W1   = (const float*)d_in[4];
    const float* b1   = (const float*)d_in[5];
    const float* W2   = (const float*)d_in[6];
    const float* b2   = (const float*)d_in[7];
    float* out = (float*)d_out;

    cudaFuncSetAttribute(interp_tc, cudaFuncAttributeMaxDynamicSharedMemorySize, ISMB);
    cudaFuncSetAttribute(mlp_tc,    cudaFuncAttributeMaxDynamicSharedMemorySize, MSMB);

    split_p2f<<<(Bn * C2n * Mn / 4) / 256, 256>>>(p2);
    dim3 grid(Nn / 64, Bn);
    interp_tc<<<grid, 256, ISMB>>>(xyz1, xyz2);
    mlp_tc<<<grid, 256, MSMB>>>(p1, W1, b1, W2, b2, out);
}

// round 12
// speedup vs baseline: 1.9370x; 1.2744x over previous
#include <cuda_runtime.h>
#include <cuda_fp16.h>
#include <cstdint>

// Problem constants
#define Bn   16
#define Nn   4096
#define Mn   1024
#define C1n  128
#define C2n  256
#define CINn 384
#define H1n  256
#define H2n  128

#define WSCALE 0.00048828125f   // 2^-11: keeps inv-dist weights < fp16 max; cancels in ratio

// ---------------- helpers ----------------
__device__ __forceinline__ uint32_t smem_u32(const void* p) {
    uint32_t a;
    asm("{ .reg .u64 t; cvta.to.shared.u64 t, %1; cvt.u32.u64 %0, t; }" : "=r"(a) : "l"(p));
    return a;
}
__device__ __forceinline__ void ldsm4(uint32_t* r, uint32_t addr) {
    asm volatile("ldmatrix.sync.aligned.m8n8.x4.shared.b16 {%0,%1,%2,%3}, [%4];"
        : "=r"(r[0]), "=r"(r[1]), "=r"(r[2]), "=r"(r[3]) : "r"(addr));
}
__device__ __forceinline__ void ldsm4t(uint32_t* r, uint32_t addr) {
    asm volatile("ldmatrix.sync.aligned.m8n8.x4.trans.shared.b16 {%0,%1,%2,%3}, [%4];"
        : "=r"(r[0]), "=r"(r[1]), "=r"(r[2]), "=r"(r[3]) : "r"(addr));
}
__device__ __forceinline__ void mma_f16(float* d, const uint32_t* a, const uint32_t* b) {
    asm volatile("mma.sync.aligned.m16n8k16.row.col.f32.f16.f16.f32 "
        "{%0,%1,%2,%3}, {%4,%5,%6,%7}, {%8,%9}, {%0,%1,%2,%3};"
        : "+f"(d[0]), "+f"(d[1]), "+f"(d[2]), "+f"(d[3])
        : "r"(a[0]), "r"(a[1]), "r"(a[2]), "r"(a[3]), "r"(b[0]), "r"(b[1]));
}
// fp16 pack of two floats (rn)
__device__ __forceinline__ uint32_t h2pack(float a, float b) {
    __half2 h = __floats2half2_rn(a, b);
    return *(uint32_t*)&h;
}
// pack + accumulate the QUANTIZED values (keeps num/den weight errors correlated)
__device__ __forceinline__ uint32_t h2pack_acc(float a, float b, float& s) {
    __half2 h = __floats2half2_rn(a, b);
    float2 f = __half22float2(h);
    s += f.x + f.y;
    return *(uint32_t*)&h;
}
#define CP16(dst, src) asm volatile("cp.async.cg.shared.global [%0], [%1], 16;" :: "r"(dst), "l"(src))
#define CPCOMMIT()     asm volatile("cp.async.commit_group;" ::: "memory")
#define CPWAIT(n)      asm volatile("cp.async.wait_group %0;" :: "n"(n) : "memory")

// device scratch
__device__ float    g_interp[(size_t)Bn * C2n * Nn];
__device__ uint16_t g_p2f[(size_t)Bn * C2n * Mn];   // p2 as fp16

// prep: p2 fp32 -> fp16
__global__ void split_p2f(const float* __restrict__ src)
{
    const size_t i = (size_t)blockIdx.x * 256 + threadIdx.x;   // float4 index
    const float4 v = ((const float4*)src)[i];
    uint2 o;
    o.x = h2pack(v.x, v.y);
    o.y = h2pack(v.z, v.w);
    ((uint2*)g_p2f)[i] = o;
}

// paired-row address: two logical 64B rows per 144B physical row (conflict-free ldsm)
#define PR(r) (((r) >> 1) * 144 + ((r) & 1) * 64)

// ================= Kernel 1: interpolation via mma.sync (fp16, 1-pass) =================
// CTA: 64 n x 256 c.  K = M = 1024 in 32-chunks, double-buffered, occ 2.
// A [64n][32k] fp16, pitch 80 (SIMT fill); B [256c][32k] fp16 (cp.async).
#define IA(buf)   ((buf) * 5120)
#define IB(buf)   (10240 + (buf) * 18432)
#define IOFF_X2   47104             // SoA: x[1024], y[1024], z[1024]
#define IOFF_DS   59392
#define IOFF_DEN  60416
#define ISMB      60672

__global__ __launch_bounds__(256, 2)
void interp_tc(const float* __restrict__ xyz1,
               const float* __restrict__ xyz2)
{
    extern __shared__ char smc[];
    const uint32_t sb = smem_u32(smc);
    float* s_x2x = (float*)(smc + IOFF_X2);
    float* s_x2y = s_x2x + Mn;
    float* s_x2z = s_x2x + 2 * Mn;
    float* s_ds  = (float*)(smc + IOFF_DS);
    float* s_den = (float*)(smc + IOFF_DEN);

    const int tid = threadIdx.x, w = tid >> 5, lane = tid & 31;
    const int b = blockIdx.y, n0 = blockIdx.x * 64;

    // xyz2 -> SoA smem
    for (int m = tid; m < Mn; m += 256) {
        const float3 v = ((const float3*)(xyz2 + (size_t)b * Mn * 3))[m];
        s_x2x[m] = v.x; s_x2y[m] = v.y; s_x2z[m] = v.z;
    }
    __syncthreads();

    const int nf = tid & 63;        // point this thread generates weights for
    const int g  = tid >> 6;        // 8-m group within 32-chunk
    const float px = xyz1[((size_t)b * Nn + n0 + nf) * 3 + 0];
    const float py = xyz1[((size_t)b * Nn + n0 + nf) * 3 + 1];
    const float pz = xyz1[((size_t)b * Nn + n0 + nf) * 3 + 2];
    float dsum = 0.f;               // sum of QUANTIZED scaled weights

    const int mw = w & 1, cw = w >> 1;   // warp tile: 32 n x 64 c
    float acc[16][4];
    #pragma unroll
    for (int i = 0; i < 16; i++)
        #pragma unroll
        for (int j = 0; j < 4; j++) acc[i][j] = 0.f;

    const size_t p2base = (size_t)b * C2n * Mn;

    // A fill: rsqrt weights (scaled) -> single fp16; dsum uses quantized values
    #define FILLA(ch) do {                                                         \
        const int _buf = (ch) & 1, _mb = (ch) * 32 + g * 8;                        \
        const float4 xa = *(const float4*)&s_x2x[_mb];                             \
        const float4 xbv = *(const float4*)&s_x2x[_mb + 4];                        \
        const float4 ya = *(const float4*)&s_x2y[_mb];                             \
        const float4 yb = *(const float4*)&s_x2y[_mb + 4];                         \
        const float4 za = *(const float4*)&s_x2z[_mb];                             \
        const float4 zb = *(const float4*)&s_x2z[_mb + 4];                         \
        const float xs[8] = {xa.x, xa.y, xa.z, xa.w, xbv.x, xbv.y, xbv.z, xbv.w};  \
        const float ys[8] = {ya.x, ya.y, ya.z, ya.w, yb.x, yb.y, yb.z, yb.w};      \
        const float zs[8] = {za.x, za.y, za.z, za.w, zb.x, zb.y, zb.z, zb.w};      \
        float iv[8];                                                               \
        _Pragma("unroll")                                                          \
        for (int t = 0; t < 8; t++) {                                              \
            const float dx = px - xs[t];                                           \
            const float dy = py - ys[t];                                           \
            const float dz = pz - zs[t];                                           \
            const float d2 = fmaf(dx, dx, fmaf(dy, dy, fmaf(dz, dz, 1e-16f)));     \
            iv[t] = rsqrtf(d2) * WSCALE;                                           \
        }                                                                          \
        uint4 hv;                                                                  \
        hv.x = h2pack_acc(iv[0], iv[1], dsum);                                     \
        hv.y = h2pack_acc(iv[2], iv[3], dsum);                                     \
        hv.z = h2pack_acc(iv[4], iv[5], dsum);                                     \
        hv.w = h2pack_acc(iv[6], iv[7], dsum);                                     \
        *(uint4*)(smc + IA(_buf) + nf * 80 + g * 16) = hv;                         \
    } while (0)

    // B fill: cp.async fp16 p2 chunk, 4 x 16B per thread
    #define FILLB(ch) do {                                                         \
        const int _buf = (ch) & 1, _m0 = (ch) * 32;                                \
        _Pragma("unroll")                                                          \
        for (int it = 0; it < 4; it++) {                                           \
            const int u = tid + it * 256;                                          \
            const int c = u >> 2, s = u & 3;                                       \
            const uint32_t dst = sb + IB(_buf) + PR(c) + s * 16;                   \
            CP16(dst, g_p2f + p2base + (size_t)c * Mn + _m0 + s * 8);              \
        }                                                                          \
        CPCOMMIT();                                                                \
    } while (0)

    FILLA(0);
    FILLB(0);

    for (int ch = 0; ch < 32; ch++) {
        const int buf = ch & 1;
        CPWAIT(0);
        __syncthreads();
        if (ch < 31) { FILLB(ch + 1); FILLA(ch + 1); }

        #pragma unroll
        for (int kk = 0; kk < 2; kk++) {
            uint32_t ah[2][4];
            #pragma unroll
            for (int mt = 0; mt < 2; mt++) {
                const uint32_t row = mw * 32 + mt * 16 + (lane & 15);
                const uint32_t off = row * 80 + kk * 32 + (lane >> 4) * 16;
                ldsm4(ah[mt], sb + IA(buf) + off);
            }
            #pragma unroll
            for (int cp = 0; cp < 4; cp++) {
                const uint32_t c = cw * 64 + cp * 16 + (lane >> 4) * 8 + (lane & 7);
                const uint32_t off = PR(c) + kk * 32 + ((lane >> 3) & 1) * 16;
                uint32_t rh[4];
                ldsm4(rh, sb + IB(buf) + off);
                #pragma unroll
                for (int mt = 0; mt < 2; mt++) {
                    mma_f16(acc[mt * 8 + cp * 2],     ah[mt], rh);
                    mma_f16(acc[mt * 8 + cp * 2 + 1], ah[mt], rh + 2);
                }
            }
        }
    }
    #undef FILLA
    #undef FILLB

    // denominator (quantized-consistent, scaled; cancels with scaled numerator)
    __syncthreads();
    s_ds[tid] = dsum;
    __syncthreads();
    if (tid < 64)
        s_den[tid] = 1.0f / (s_ds[tid] + s_ds[tid + 64] + s_ds[tid + 128] + s_ds[tid + 192]);
    __syncthreads();

    // epilogue: scale and store
    #pragma unroll
    for (int mt = 0; mt < 2; mt++) {
        const int nl = mw * 32 + mt * 16 + (lane >> 2);
        const float i0 = s_den[nl], i1 = s_den[nl + 8];
        #pragma unroll
        for (int ct = 0; ct < 8; ct++) {
            const int c = cw * 64 + ct * 8 + (lane & 3) * 2;
            float* d0 = &g_interp[((size_t)b * C2n + c) * Nn + n0];
            float* d1 = &g_interp[((size_t)b * C2n + c + 1) * Nn + n0];
            const float* a = acc[mt * 8 + ct];
            d0[nl]     = a[0] * i0;
            d1[nl]     = a[1] * i0;
            d0[nl + 8] = a[2] * i1;
            d1[nl + 8] = a[3] * i1;
        }
    }
}

// ================= Kernel 2: fused 2-layer MLP (fp16, 1-pass) =================
// CTA: 64 n. GEMM1: 256o x 64n x K384 (32-chunks); GEMM2: 128o x 64n x K256.
#define MW(buf)    ((buf) * 18432)                 // W1 chunk [256o][32k] paired rows
#define MH         0                               // h [256k][64n] fp16 (overlays MW, 36864 B)
#define MW2(buf)   (36864 + (buf) * 9216)          // W2 chunk [128o][32k] paired rows
#define MX(buf)    (55296 + (buf) * 4608)          // x chunk [32k][64n] fp16
#define MOFF_B1    64512
#define MOFF_B2    65536
#define MSMB       66048

__global__ __launch_bounds__(256, 2)
void mlp_tc(const float* __restrict__ p1,
            const float* __restrict__ W1,
            const float* __restrict__ b1,
            const float* __restrict__ W2,
            const float* __restrict__ b2,
            float* __restrict__ out)
{
    extern __shared__ char smc[];
    const uint32_t sb = smem_u32(smc);
    float* s_b1 = (float*)(smc + MOFF_B1);
    float* s_b2 = (float*)(smc + MOFF_B2);

    const int tid = threadIdx.x, w = tid >> 5, lane = tid & 31;
    const int b = blockIdx.y, n0 = blockIdx.x * 64;

    s_b1[tid] = b1[tid];
    if (tid < H2n) s_b2[tid] = b2[tid];

    const int ow = w >> 1, nw = w & 1;   // GEMM1 warp: 64 o x 32 n

    #define FILLW1(kc) do {                                                         \
        const int _buf = (kc) & 1;                                                  \
        _Pragma("unroll")                                                           \
        for (int it = 0; it < 8; it++) {                                            \
            const int u = tid + it * 256;                                           \
            const int o = u >> 3, q = u & 7;                                        \
            const float4 v = *(const float4*)&W1[(size_t)o * CINn + (kc) * 32 + q * 4]; \
            uint2 hv;                                                               \
            hv.x = h2pack(v.x, v.y);                                                \
            hv.y = h2pack(v.z, v.w);                                                \
            *(uint2*)(smc + MW(_buf) + PR(o) + q * 8) = hv;                         \
        }                                                                           \
    } while (0)

    #define FILLX(kc) do {                                                          \
        const int _buf = (kc) & 1;                                                  \
        const int k = tid >> 3, q = tid & 7;                                        \
        const int c = (kc) * 32 + k;                                                \
        const float* src = (c < C1n)                                                \
            ? &p1[((size_t)b * C1n + c) * Nn]                                       \
            : &g_interp[((size_t)b * C2n + (c - C1n)) * Nn];                        \
        const float4 v0 = *(const float4*)&src[n0 + q * 8];                         \
        const float4 v1 = *(const float4*)&src[n0 + q * 8 + 4];                     \
        uint4 xv;                                                                   \
        xv.x = h2pack(v0.x, v0.y); xv.y = h2pack(v0.z, v0.w);                       \
        xv.z = h2pack(v1.x, v1.y); xv.w = h2pack(v1.z, v1.w);                       \
        *(uint4*)(smc + MX(_buf) + k * 144 + q * 16) = xv;                          \
    } while (0)

    float acc1[16][4];
    #pragma unroll
    for (int i = 0; i < 16; i++)
        #pragma unroll
        for (int j = 0; j < 4; j++) acc1[i][j] = 0.f;

    FILLW1(0); FILLX(0);
    __syncthreads();

    for (int kc = 0; kc < 12; kc++) {
        const int buf = kc & 1;
        #pragma unroll
        for (int kk = 0; kk < 2; kk++) {
            uint32_t wh[4][4];
            #pragma unroll
            for (int mi = 0; mi < 4; mi++) {
                const uint32_t o = ow * 64 + mi * 16 + (lane & 15);
                const uint32_t off = PR(o) + kk * 32 + (lane >> 4) * 16;
                ldsm4(wh[mi], sb + MW(buf) + off);
            }
            uint32_t xh[4][2];
            #pragma unroll
            for (int np = 0; np < 2; np++) {
                const uint32_t row  = kk * 16 + ((lane >> 3) & 1) * 8 + (lane & 7);
                const uint32_t colb = (nw * 32 + np * 16) * 2 + (lane >> 4) * 16;
                uint32_t r[4];
                ldsm4t(r, sb + MX(buf) + row * 144 + colb);
                xh[np * 2][0] = r[0]; xh[np * 2][1] = r[1];
                xh[np * 2 + 1][0] = r[2]; xh[np * 2 + 1][1] = r[3];
            }
            #pragma unroll
            for (int mi = 0; mi < 4; mi++)
                #pragma unroll
                for (int ni = 0; ni < 4; ni++)
                    mma_f16(acc1[mi * 4 + ni], wh[mi], xh[ni]);
        }
        if (kc < 11) { FILLW1(kc + 1); FILLX(kc + 1); }
        __syncthreads();
    }
    #undef FILLW1
    #undef FILLX

    #define FILLW2(kc) do {                                                         \
        const int _buf = (kc) & 1;                                                  \
        _Pragma("unroll")                                                           \
        for (int it = 0; it < 4; it++) {                                            \
            const int u = tid + it * 256;                                           \
            const int o = u >> 3, q = u & 7;                                        \
            const float4 v = *(const float4*)&W2[(size_t)o * H1n + (kc) * 32 + q * 4]; \
            uint2 hv;                                                               \
            hv.x = h2pack(v.x, v.y);                                                \
            hv.y = h2pack(v.z, v.w);                                                \
            *(uint2*)(smc + MW2(_buf) + PR(o) + q * 8) = hv;                        \
        }                                                                           \
    } while (0)

    // W1/x regions fully read; repurpose for W2 + h
    FILLW2(0);

    // GEMM1 epilogue: relu + bias -> s_h [256 k-rows][64 n], fp16 (overlays MW)
    #pragma unroll
    for (int mi = 0; mi < 4; mi++) {
        const int o = ow * 64 + mi * 16 + (lane >> 2);
        const float bia0 = s_b1[o], bia1 = s_b1[o + 8];
        #pragma unroll
        for (int ni = 0; ni < 4; ni++) {
            const int n = nw * 32 + ni * 8 + (lane & 3) * 2;
            const float* a = acc1[mi * 4 + ni];
            const float v0 = fmaxf(a[0] + bia0, 0.f);
            const float v1 = fmaxf(a[1] + bia0, 0.f);
            const float v2 = fmaxf(a[2] + bia1, 0.f);
            const float v3 = fmaxf(a[3] + bia1, 0.f);
            *(uint32_t*)(smc + MH + o * 144 + n * 2)       = h2pack(v0, v1);
            *(uint32_t*)(smc + MH + (o + 8) * 144 + n * 2) = h2pack(v2, v3);
        }
    }
    __syncthreads();

    // ---------- GEMM2 (distance-1 double buffer) ----------
    const int ow2 = w >> 1;   // 32 o per warp
    float acc2[8][4];
    #pragma unroll
    for (int i = 0; i < 8; i++)
        #pragma unroll
        for (int j = 0; j < 4; j++) acc2[i][j] = 0.f;

    for (int kc = 0; kc < 8; kc++) {
        const int buf = kc & 1;
        #pragma unroll
        for (int kk = 0; kk < 2; kk++) {
            uint32_t wh[2][4];
            #pragma unroll
            for (int mi = 0; mi < 2; mi++) {
                const uint32_t o = ow2 * 32 + mi * 16 + (lane & 15);
                const uint32_t off = PR(o) + kk * 32 + (lane >> 4) * 16;
                ldsm4(wh[mi], sb + MW2(buf) + off);
            }
            uint32_t hh[4][2];
            #pragma unroll
            for (int np = 0; np < 2; np++) {
                const uint32_t row  = kc * 32 + kk * 16 + ((lane >> 3) & 1) * 8 + (lane & 7);
                const uint32_t colb = (nw * 32 + np * 16) * 2 + (lane >> 4) * 16;
                uint32_t r[4];
                ldsm4t(r, sb + MH + row * 144 + colb);
                hh[np * 2][0] = r[0]; hh[np * 2][1] = r[1];
                hh[np * 2 + 1][0] = r[2]; hh[np * 2 + 1][1] = r[3];
            }
            #pragma unroll
            for (int mi = 0; mi < 2; mi++)
                #pragma unroll
                for (int ni = 0; ni < 4; ni++)
                    mma_f16(acc2[mi * 4 + ni], wh[mi], hh[ni]);
        }
        if (kc < 7) FILLW2(kc + 1);   // writes OTHER buffer — safe
        __syncthreads();
    }
    #undef FILLW2

    // ---------- output ----------
    #pragma unroll
    for (int mi = 0; mi < 2; mi++) {
        const int o = ow2 * 32 + mi * 16 + (lane >> 2);
        const float bia0 = s_b2[o], bia1 = s_b2[o + 8];
        #pragma unroll
        for (int ni = 0; ni < 4; ni++) {
            const int n = n0 + nw * 32 + ni * 8 + (lane & 3) * 2;
            const float* a = acc2[mi * 4 + ni];
            float2 v0, v1;
            v0.x = fmaxf(a[0] + bia0, 0.f);
            v0.y = fmaxf(a[1] + bia0, 0.f);
            v1.x = fmaxf(a[2] + bia1, 0.f);
            v1.y = fmaxf(a[3] + bia1, 0.f);
            *(float2*)&out[((size_t)b * H2n + o) * Nn + n]     = v0;
            *(float2*)&out[((size_t)b * H2n + o + 8) * Nn + n] = v1;
        }
    }
}

extern "C" void kernel_launch(void* const* d_in, const int* in_sizes, int n_in,
                              void* d_out, int out_size)
{
    const float* xyz1 = (const float*)d_in[0];
    const float* xyz2 = (const float*)d_in[1];
    const float* p1   = (const float*)d_in[2];
    const float* p2   = (const float*)d_in[3];
    const float* W1   = (const float*)d_in[4];
    const float* b1   = (const float*)d_in[5];
    const float* W2   = (const float*)d_in[6];
    const float* b2   = (const float*)d_in[7];
    float* out = (float*)d_out;

    cudaFuncSetAttribute(interp_tc, cudaFuncAttributeMaxDynamicSharedMemorySize, ISMB);
    cudaFuncSetAttribute(mlp_tc,    cudaFuncAttributeMaxDynamicSharedMemorySize, MSMB);

    split_p2f<<<(Bn * C2n * Mn / 4) / 256, 256>>>(p2);
    dim3 grid(Nn / 64, Bn);
    interp_tc<<<grid, 256, ISMB>>>(xyz1, xyz2);
    mlp_tc<<<grid, 256, MSMB>>>(p1, W1, b1, W2, b2, out);
}

// round 13
// speedup vs baseline: 2.0965x; 1.0823x over previous
#include <cuda_runtime.h>
#include <cuda_fp16.h>
#include <cstdint>

// Problem constants
#define Bn   16
#define Nn   4096
#define Mn   1024
#define C1n  128
#define C2n  256
#define CINn 384
#define H1n  256
#define H2n  128

#define WSCALE 0.00048828125f   // 2^-11: keeps inv-dist weights < fp16 max; cancels in ratio

// ---------------- helpers ----------------
__device__ __forceinline__ uint32_t smem_u32(const void* p) {
    uint32_t a;
    asm("{ .reg .u64 t; cvta.to.shared.u64 t, %1; cvt.u32.u64 %0, t; }" : "=r"(a) : "l"(p));
    return a;
}
__device__ __forceinline__ void ldsm4(uint32_t* r, uint32_t addr) {
    asm volatile("ldmatrix.sync.aligned.m8n8.x4.shared.b16 {%0,%1,%2,%3}, [%4];"
        : "=r"(r[0]), "=r"(r[1]), "=r"(r[2]), "=r"(r[3]) : "r"(addr));
}
__device__ __forceinline__ void ldsm4t(uint32_t* r, uint32_t addr) {
    asm volatile("ldmatrix.sync.aligned.m8n8.x4.trans.shared.b16 {%0,%1,%2,%3}, [%4];"
        : "=r"(r[0]), "=r"(r[1]), "=r"(r[2]), "=r"(r[3]) : "r"(addr));
}
__device__ __forceinline__ void mma_f16(float* d, const uint32_t* a, const uint32_t* b) {
    asm volatile("mma.sync.aligned.m16n8k16.row.col.f32.f16.f16.f32 "
        "{%0,%1,%2,%3}, {%4,%5,%6,%7}, {%8,%9}, {%0,%1,%2,%3};"
        : "+f"(d[0]), "+f"(d[1]), "+f"(d[2]), "+f"(d[3])
        : "r"(a[0]), "r"(a[1]), "r"(a[2]), "r"(a[3]), "r"(b[0]), "r"(b[1]));
}
__device__ __forceinline__ uint32_t h2pack(float a, float b) {
    __half2 h = __floats2half2_rn(a, b);
    return *(uint32_t*)&h;
}
// pack + accumulate the QUANTIZED values (keeps num/den weight errors correlated)
__device__ __forceinline__ uint32_t h2pack_acc(float a, float b, float& s) {
    __half2 h = __floats2half2_rn(a, b);
    float2 f = __half22float2(h);
    s += f.x + f.y;
    return *(uint32_t*)&h;
}
#define CP16(dst, src) asm volatile("cp.async.cg.shared.global [%0], [%1], 16;" :: "r"(dst), "l"(src))
#define CPCOMMIT()     asm volatile("cp.async.commit_group;" ::: "memory")
#define CPWAIT(n)      asm volatile("cp.async.wait_group %0;" :: "n"(n) : "memory")

// device scratch (fp16 as u16)
__device__ uint16_t g_p2f[(size_t)Bn * C2n * Mn];
__device__ uint16_t g_p1f[(size_t)Bn * C1n * Nn];

// prep: fp32 -> fp16
__global__ void tofp16(const float* __restrict__ src, uint16_t* __restrict__ dst)
{
    const size_t i = (size_t)blockIdx.x * 256 + threadIdx.x;   // float4 index
    const float4 v = ((const float4*)src)[i];
    uint2 o;
    o.x = h2pack(v.x, v.y);
    o.y = h2pack(v.z, v.w);
    ((uint2*)dst)[i] = o;
}

// paired-row address: two logical 64B rows per 144B physical row (conflict-free ldsm)
#define PR(r) (((r) >> 1) * 144 + ((r) & 1) * 64)

// ================= Fused kernel: interp (fp16 mma) + 2-layer MLP =================
// CTA: 64 n. Phase 1: interp 64n x 256c over K=M=1024 (32-chunks, dbl-buffered),
// result written as fp16 straight into the resident x-tile (rows 128..383);
// rows 0..127 cp.async'd from prequantized p1 during phase 1.
// Phase 2: GEMM1 256o x 64n x K384 (x resident), GEMM2 128o x 64n x K256.
//
// SMEM map (bytes):
//   [0, 55296)           x tile [384 rows][144]  (fp16, resident both phases)
//   [55296, 114688)      workspace WS:
//     interp: IA 2x5120, IB 2x18432 (-> +47104), xyz SoA 12288 (-> +59392)
//             s_ds/s_den overlay IA(0) after the loop
//     mlp:    MW 2x18432 (h overlays), MW2 2x9216 (-> +55296),
//             b1/b2 overlay the xyz region
#define XOFF  0
#define WS    55296
#define IA(buf)   (WS + (buf) * 5120)
#define IB(buf)   (WS + 10240 + (buf) * 18432)
#define IX2       (WS + 47104)
#define MW(buf)   (WS + (buf) * 18432)
#define MH        (WS)
#define MW2(buf)  (WS + 36864 + (buf) * 9216)
#define B1OFF     (WS + 55296)
#define B2OFF     (WS + 56320)
#define ISMB      114688

__global__ __launch_bounds__(256, 2)
void fp_fused(const float* __restrict__ xyz1,
              const float* __restrict__ xyz2,
              const float* __restrict__ W1,
              const float* __restrict__ b1,
              const float* __restrict__ W2,
              const float* __restrict__ b2,
              float* __restrict__ out)
{
    extern __shared__ char smc[];
    const uint32_t sb = smem_u32(smc);
    float* s_x2x = (float*)(smc + IX2);
    float* s_x2y = s_x2x + Mn;
    float* s_x2z = s_x2x + 2 * Mn;
    float* s_ds  = (float*)(smc + WS);          // overlays IA(0), used post-loop
    float* s_den = (float*)(smc + WS + 1024);
    float* s_b1  = (float*)(smc + B1OFF);
    float* s_b2  = (float*)(smc + B2OFF);

    const int tid = threadIdx.x, w = tid >> 5, lane = tid & 31;
    const int b = blockIdx.y, n0 = blockIdx.x * 64;

    // xyz2 -> SoA smem
    for (int m = tid; m < Mn; m += 256) {
        const float3 v = ((const float3*)(xyz2 + (size_t)b * Mn * 3))[m];
        s_x2x[m] = v.x; s_x2y[m] = v.y; s_x2z[m] = v.z;
    }

    // x rows 0..127 from prequantized p1 (overlaps entire interp phase)
    #pragma unroll
    for (int it = 0; it < 4; it++) {
        const int u = tid + it * 256;           // 0..1023
        const int row = u >> 3, s = u & 7;
        CP16(sb + XOFF + row * 144 + s * 16,
             g_p1f + ((size_t)b * C1n + row) * Nn + n0 + s * 8);
    }
    __syncthreads();   // xyz visible

    const int nf = tid & 63;
    const int g  = tid >> 6;
    const float px = xyz1[((size_t)b * Nn + n0 + nf) * 3 + 0];
    const float py = xyz1[((size_t)b * Nn + n0 + nf) * 3 + 1];
    const float pz = xyz1[((size_t)b * Nn + n0 + nf) * 3 + 2];
    float dsum = 0.f;

    const int mw = w & 1, cw = w >> 1;   // interp warp tile: 32 n x 64 c
    float acc[16][4];
    #pragma unroll
    for (int i = 0; i < 16; i++)
        #pragma unroll
        for (int j = 0; j < 4; j++) acc[i][j] = 0.f;

    const size_t p2base = (size_t)b * C2n * Mn;

    #define FILLA(ch) do {                                                         \
        const int _buf = (ch) & 1, _mb = (ch) * 32 + g * 8;                        \
        const float4 xa = *(const float4*)&s_x2x[_mb];                             \
        const float4 xbv = *(const float4*)&s_x2x[_mb + 4];                        \
        const float4 ya = *(const float4*)&s_x2y[_mb];                             \
        const float4 yb = *(const float4*)&s_x2y[_mb + 4];                         \
        const float4 za = *(const float4*)&s_x2z[_mb];                             \
        const float4 zb = *(const float4*)&s_x2z[_mb + 4];                         \
        const float xs[8] = {xa.x, xa.y, xa.z, xa.w, xbv.x, xbv.y, xbv.z, xbv.w};  \
        const float ys[8] = {ya.x, ya.y, ya.z, ya.w, yb.x, yb.y, yb.z, yb.w};      \
        const float zs[8] = {za.x, za.y, za.z, za.w, zb.x, zb.y, zb.z, zb.w};      \
        float iv[8];                                                               \
        _Pragma("unroll")                                                          \
        for (int t = 0; t < 8; t++) {                                              \
            const float dx = px - xs[t];                                           \
            const float dy = py - ys[t];                                           \
            const float dz = pz - zs[t];                                           \
            const float d2 = fmaf(dx, dx, fmaf(dy, dy, fmaf(dz, dz, 1e-16f)));     \
            iv[t] = rsqrtf(d2) * WSCALE;                                           \
        }                                                                          \
        uint4 hv;                                                                  \
        hv.x = h2pack_acc(iv[0], iv[1], dsum);                                     \
        hv.y = h2pack_acc(iv[2], iv[3], dsum);                                     \
        hv.z = h2pack_acc(iv[4], iv[5], dsum);                                     \
        hv.w = h2pack_acc(iv[6], iv[7], dsum);                                     \
        *(uint4*)(smc + IA(_buf) + nf * 80 + g * 16) = hv;                         \
    } while (0)

    #define FILLB(ch) do {                                                         \
        const int _buf = (ch) & 1, _m0 = (ch) * 32;                                \
        _Pragma("unroll")                                                          \
        for (int it = 0; it < 4; it++) {                                           \
            const int u = tid + it * 256;                                          \
            const int c = u >> 2, s = u & 3;                                       \
            CP16(sb + IB(_buf) + PR(c) + s * 16,                                   \
                 g_p2f + p2base + (size_t)c * Mn + _m0 + s * 8);                   \
        }                                                                          \
        CPCOMMIT();                                                                \
    } while (0)

    FILLA(0);
    FILLB(0);   // commit group also covers the p1 cp.asyncs

    for (int ch = 0; ch < 32; ch++) {
        const int buf = ch & 1;
        CPWAIT(0);
        __syncthreads();
        if (ch < 31) { FILLB(ch + 1); FILLA(ch + 1); }

        #pragma unroll
        for (int kk = 0; kk < 2; kk++) {
            uint32_t ah[2][4];
            #pragma unroll
            for (int mt = 0; mt < 2; mt++) {
                const uint32_t row = mw * 32 + mt * 16 + (lane & 15);
                const uint32_t off = row * 80 + kk * 32 + (lane >> 4) * 16;
                ldsm4(ah[mt], sb + IA(buf) + off);
            }
            #pragma unroll
            for (int cp = 0; cp < 4; cp++) {
                const uint32_t c = cw * 64 + cp * 16 + (lane >> 4) * 8 + (lane & 7);
                const uint32_t off = PR(c) + kk * 32 + ((lane >> 3) & 1) * 16;
                uint32_t rh[4];
                ldsm4(rh, sb + IB(buf) + off);
                #pragma unroll
                for (int mt = 0; mt < 2; mt++) {
                    mma_f16(acc[mt * 8 + cp * 2],     ah[mt], rh);
                    mma_f16(acc[mt * 8 + cp * 2 + 1], ah[mt], rh + 2);
                }
            }
        }
    }
    #undef FILLA
    #undef FILLB

    // denominator (quantized-consistent, scaled)
    __syncthreads();
    s_ds[tid] = dsum;
    if (tid < 64) {
        // biases load (region dead: old xyz space)
        s_b1[tid] = b1[tid]; s_b1[tid + 64] = b1[tid + 64];
        s_b1[tid + 128] = b1[tid + 128]; s_b1[tid + 192] = b1[tid + 192];
        s_b2[tid] = b2[tid]; s_b2[tid + 64] = b2[tid + 64];
    }
    __syncthreads();
    if (tid < 64)
        s_den[tid] = 1.0f / (s_ds[tid] + s_ds[tid + 64] + s_ds[tid + 128] + s_ds[tid + 192]);
    __syncthreads();

    // interp epilogue: write x rows 128..383 as fp16 (direct into resident x-tile)
    #pragma unroll
    for (int mt = 0; mt < 2; mt++) {
        const int nl = mw * 32 + mt * 16 + (lane >> 2);
        const float i0 = s_den[nl], i1 = s_den[nl + 8];
        #pragma unroll
        for (int ct = 0; ct < 8; ct++) {
            const int c = cw * 64 + ct * 8 + (lane & 3) * 2;
            const float* a = acc[mt * 8 + ct];
            __half* r0 = (__half*)(smc + XOFF + (128 + c) * 144);
            __half* r1 = (__half*)(smc + XOFF + (129 + c) * 144);
            r0[nl]     = __float2half_rn(a[0] * i0);
            r1[nl]     = __float2half_rn(a[1] * i0);
            r0[nl + 8] = __float2half_rn(a[2] * i1);
            r1[nl + 8] = __float2half_rn(a[3] * i1);
        }
    }
    __syncthreads();   // x complete; interp workspace dead

    // ================= Phase 2: MLP =================
    const int ow = w >> 1, nw = w & 1;   // GEMM1 warp: 64 o x 32 n

    #define FILLW1(kc) do {                                                         \
        const int _buf = (kc) & 1;                                                  \
        _Pragma("unroll")                                                           \
        for (int it = 0; it < 8; it++) {                                            \
            const int u = tid + it * 256;                                           \
            const int o = u >> 3, q = u & 7;                                        \
            const float4 v = *(const float4*)&W1[(size_t)o * CINn + (kc) * 32 + q * 4]; \
            uint2 hv;                                                               \
            hv.x = h2pack(v.x, v.y);                                                \
            hv.y = h2pack(v.z, v.w);                                                \
            *(uint2*)(smc + MW(_buf) + PR(o) + q * 8) = hv;                         \
        }                                                                           \
    } while (0)

    // reuse acc as acc1
    #pragma unroll
    for (int i = 0; i < 16; i++)
        #pragma unroll
        for (int j = 0; j < 4; j++) acc[i][j] = 0.f;

    FILLW1(0);
    __syncthreads();

    for (int kc = 0; kc < 12; kc++) {
        const int buf = kc & 1;
        #pragma unroll
        for (int kk = 0; kk < 2; kk++) {
            uint32_t wh[4][4];
            #pragma unroll
            for (int mi = 0; mi < 4; mi++) {
                const uint32_t o = ow * 64 + mi * 16 + (lane & 15);
                const uint32_t off = PR(o) + kk * 32 + (lane >> 4) * 16;
                ldsm4(wh[mi], sb + MW(buf) + off);
            }
            uint32_t xh[4][2];
            #pragma unroll
            for (int np = 0; np < 2; np++) {
                const uint32_t row  = kc * 32 + kk * 16 + ((lane >> 3) & 1) * 8 + (lane & 7);
                const uint32_t colb = (nw * 32 + np * 16) * 2 + (lane >> 4) * 16;
                uint32_t r[4];
                ldsm4t(r, sb + XOFF + row * 144 + colb);
                xh[np * 2][0] = r[0]; xh[np * 2][1] = r[1];
                xh[np * 2 + 1][0] = r[2]; xh[np * 2 + 1][1] = r[3];
            }
            #pragma unroll
            for (int mi = 0; mi < 4; mi++)
                #pragma unroll
                for (int ni = 0; ni < 4; ni++)
                    mma_f16(acc[mi * 4 + ni], wh[mi], xh[ni]);
        }
        if (kc < 11) FILLW1(kc + 1);
        __syncthreads();
    }
    #undef FILLW1

    #define FILLW2(kc) do {                                                         \
        const int _buf = (kc) & 1;                                                  \
        _Pragma("unroll")                                                           \
        for (int it = 0; it < 4; it++) {                                            \
            const int u = tid + it * 256;                                           \
            const int o = u >> 3, q = u & 7;                                        \
            const float4 v = *(const float4*)&W2[(size_t)o * H1n + (kc) * 32 + q * 4]; \
            uint2 hv;                                                               \
            hv.x = h2pack(v.x, v.y);                                                \
            hv.y = h2pack(v.z, v.w);                                                \
            *(uint2*)(smc + MW2(_buf) + PR(o) + q * 8) = hv;                        \
        }                                                                           \
    } while (0)

    FILLW2(0);

    // GEMM1 epilogue: relu + bias -> h [256 k-rows][64 n] fp16 (overlays MW)
    #pragma unroll
    for (int mi = 0; mi < 4; mi++) {
        const int o = ow * 64 + mi * 16 + (lane >> 2);
        const float bia0 = s_b1[o], bia1 = s_b1[o + 8];
        #pragma unroll
        for (int ni = 0; ni < 4; ni++) {
            const int n = nw * 32 + ni * 8 + (lane & 3) * 2;
            const float* a = acc[mi * 4 + ni];
            const float v0 = fmaxf(a[0] + bia0, 0.f);
            const float v1 = fmaxf(a[1] + bia0, 0.f);
            const float v2 = fmaxf(a[2] + bia1, 0.f);
            const float v3 = fmaxf(a[3] + bia1, 0.f);
            *(uint32_t*)(smc + MH + o * 144 + n * 2)       = h2pack(v0, v1);
            *(uint32_t*)(smc + MH + (o + 8) * 144 + n * 2) = h2pack(v2, v3);
        }
    }
    __syncthreads();

    // GEMM2 (distance-1 double buffer)
    const int ow2 = w >> 1;
    float acc2[8][4];
    #pragma unroll
    for (int i = 0; i < 8; i++)
        #pragma unroll
        for (int j = 0; j < 4; j++) acc2[i][j] = 0.f;

    for (int kc = 0; kc < 8; kc++) {
        const int buf = kc & 1;
        #pragma unroll
        for (int kk = 0; kk < 2; kk++) {
            uint32_t wh[2][4];
            #pragma unroll
            for (int mi = 0; mi < 2; mi++) {
                const uint32_t o = ow2 * 32 + mi * 16 + (lane & 15);
                const uint32_t off = PR(o) + kk * 32 + (lane >> 4) * 16;
                ldsm4(wh[mi], sb + MW2(buf) + off);
            }
            uint32_t hh[4][2];
            #pragma unroll
            for (int np = 0; np < 2; np++) {
                const uint32_t row  = kc * 32 + kk * 16 + ((lane >> 3) & 1) * 8 + (lane & 7);
                const uint32_t colb = (nw * 32 + np * 16) * 2 + (lane >> 4) * 16;
                uint32_t r[4];
                ldsm4t(r, sb + MH + row * 144 + colb);
                hh[np * 2][0] = r[0]; hh[np * 2][1] = r[1];
                hh[np * 2 + 1][0] = r[2]; hh[np * 2 + 1][1] = r[3];
            }
            #pragma unroll
            for (int mi = 0; mi < 2; mi++)
                #pragma unroll
                for (int ni = 0; ni < 4; ni++)
                    mma_f16(acc2[mi * 4 + ni], wh[mi], hh[ni]);
        }
        if (kc < 7) FILLW2(kc + 1);   // writes OTHER buffer — safe
        __syncthreads();
    }
    #undef FILLW2

    // output
    #pragma unroll
    for (int mi = 0; mi < 2; mi++) {
        const int o = ow2 * 32 + mi * 16 + (lane >> 2);
        const float bia0 = s_b2[o], bia1 = s_b2[o + 8];
        #pragma unroll
        for (int ni = 0; ni < 4; ni++) {
            const int n = n0 + nw * 32 + ni * 8 + (lane & 3) * 2;
            const float* a = acc2[mi * 4 + ni];
            float2 v0, v1;
            v0.x = fmaxf(a[0] + bia0, 0.f);
            v0.y = fmaxf(a[1] + bia0, 0.f);
            v1.x = fmaxf(a[2] + bia1, 0.f);
            v1.y = fmaxf(a[3] + bia1, 0.f);
            *(float2*)&out[((size_t)b * H2n + o) * Nn + n]     = v0;
            *(float2*)&out[((size_t)b * H2n + o + 8) * Nn + n] = v1;
        }
    }
}

extern "C" void kernel_launch(void* const* d_in, const int* in_sizes, int n_in,
                              void* d_out, int out_size)
{
    const float* xyz1 = (const float*)d_in[0];
    const float* xyz2 = (const float*)d_in[1];
    const float* p1   = (const float*)d_in[2];
    const float* p2   = (const float*)d_in[3];
    const float* W1   = (const float*)d_in[4];
    const float* b1   = (const float*)d_in[5];
    const float* W2   = (const float*)d_in[6];
    const float* b2   = (const float*)d_in[7];
    float* out = (float*)d_out;

    cudaFuncSetAttribute(fp_fused, cudaFuncAttributeMaxDynamicSharedMemorySize, ISMB);

    uint16_t* p2f; cudaGetSymbolAddress((void**)&p2f, g_p2f);
    uint16_t* p1f; cudaGetSymbolAddress((void**)&p1f, g_p1f);

    tofp16<<<(Bn * C2n * Mn / 4) / 256, 256>>>(p2, p2f);
    tofp16<<<(Bn * C1n * Nn / 4) / 256, 256>>>(p1, p1f);

    dim3 grid(Nn / 64, Bn);
    fp_fused<<<grid, 256, ISMB>>>(xyz1, xyz2, W1, b1, W2, b2, out);
}